// round 11
// baseline (speedup 1.0000x reference)
#include <cuda_runtime.h>
#include <cuda_bf16.h>
#include <cstdint>

// Problem constants
#define Bz   8
#define TQ   64
#define TK   128
#define Dd   512
#define Vv   32000
#define EXTN (Vv + TK)      // 32128
#define NROW (Bz * TQ)      // 512
#define NKROW (Bz * TK)     // 1024

// ---------------- scratch (device globals; ~3.3 MB total) --------------------
__device__ float g_qproj[NROW * Dd];
__device__ float g_kproj[NKROW * Dd];
__device__ float g_att[NROW * TK];
__device__ float g_p[NROW];
__device__ float g_rowsum[NROW];
__device__ float g_rowsq[NROW];
__device__ float g_srcmask[NKROW];
__device__ float g_tgtmask[NROW];

// ---------------- generic helpers -------------------------------------------
__device__ __forceinline__ float warp_sum(float v) {
#pragma unroll
    for (int o = 16; o > 0; o >>= 1) v += __shfl_xor_sync(0xffffffffu, v, o);
    return v;
}
__device__ __forceinline__ float warp_max(float v) {
#pragma unroll
    for (int o = 16; o > 0; o >>= 1) v = fmaxf(v, __shfl_xor_sync(0xffffffffu, v, o));
    return v;
}
__device__ __forceinline__ float block_sum256(float v, float* scr) {
    v = warp_sum(v);
    int w = threadIdx.x >> 5;
    __syncthreads();
    if ((threadIdx.x & 31) == 0) scr[w] = v;
    __syncthreads();
    if (threadIdx.x == 0) {
        float t = 0.f;
#pragma unroll
        for (int i = 0; i < 8; i++) t += scr[i];
        scr[8] = t;
    }
    __syncthreads();
    return scr[8];
}
__device__ __forceinline__ float block_max256(float v, float* scr) {
    v = warp_max(v);
    int w = threadIdx.x >> 5;
    __syncthreads();
    if ((threadIdx.x & 31) == 0) scr[w] = v;
    __syncthreads();
    if (threadIdx.x == 0) {
        float t = scr[0];
#pragma unroll
        for (int i = 1; i < 8; i++) t = fmaxf(t, scr[i]);
        scr[8] = t;
    }
    __syncthreads();
    return scr[8];
}

// FMA-only tanh (proven; MUFU tanh would be throughput-bound at 33.5M calls)
__device__ __forceinline__ float tanh_fast(float x) {
    float z = x * 2.885390081777927f;             // 2x * log2(e)
    z = fminf(25.f, fmaxf(-25.f, z));
    const float big = 12582912.f;                 // 1.5 * 2^23
    float t  = z + big;
    float nf = t - big;
    float f  = z - nf;
    int   n  = __float_as_int(t) - 0x4B400000;
    float p = 1.33335581e-3f;
    p = fmaf(p, f, 9.61804886e-3f);
    p = fmaf(p, f, 5.55041087e-2f);
    p = fmaf(p, f, 2.40226337e-1f);
    p = fmaf(p, f, 6.93147182e-1f);
    p = fmaf(p, f, 1.0f);
    float y = __int_as_float(__float_as_int(p) + (n << 23));  // e^{2x}
    float d = y + 1.f;
    float r = __int_as_float((int)(0x7EF127EAu - (unsigned)__float_as_int(d)));
    r = r * fmaf(-d, r, 2.f);
    r = r * fmaf(-d, r, 2.f);
    r = r * fmaf(-d, r, 2.f);
    return (y - 1.f) * r;
}
__device__ __forceinline__ uint32_t smem_u32(const void* p) {
    uint32_t a;
    asm("{ .reg .u64 t; cvta.to.shared.u64 t, %1; cvt.u32.u64 %0, t; }"
        : "=r"(a) : "l"(p));
    return a;
}

// value-only fragment types
struct U4 { uint32_t x, y, z, w; };
struct F4 { float x, y, z, w; };

__device__ __forceinline__ U4 ldmx4(uint32_t addr) {
    U4 r;
    asm volatile("ldmatrix.sync.aligned.m8n8.x4.shared.b16 {%0,%1,%2,%3}, [%4];"
                 : "=r"(r.x), "=r"(r.y), "=r"(r.z), "=r"(r.w) : "r"(addr));
    return r;
}
__device__ __forceinline__ void mma(F4& d, const U4& a, uint32_t b0, uint32_t b1) {
    asm volatile("mma.sync.aligned.m16n8k16.row.col.f32.bf16.bf16.f32 "
        "{%0,%1,%2,%3}, {%4,%5,%6,%7}, {%8,%9}, {%0,%1,%2,%3};"
        : "+f"(d.x), "+f"(d.y), "+f"(d.z), "+f"(d.w)
        : "r"(a.x), "r"(a.y), "r"(a.z), "r"(a.w), "r"(b0), "r"(b1));
}
__device__ __forceinline__ void sts16(uint32_t addr, uint32_t v0, uint32_t v1,
                                      uint32_t v2, uint32_t v3) {
    asm volatile("st.shared.v4.u32 [%0], {%1, %2, %3, %4};"
                 :: "r"(addr), "r"(v0), "r"(v1), "r"(v2), "r"(v3));
}

// fp32x4 -> packed bf16x2 hi / lo (split: x = hi + lo)
__device__ __forceinline__ void split4(float4 v, uint2& h, uint2& l) {
    __nv_bfloat16 h0 = __float2bfloat16(v.x), h1 = __float2bfloat16(v.y);
    __nv_bfloat16 h2 = __float2bfloat16(v.z), h3 = __float2bfloat16(v.w);
    __nv_bfloat16 a0 = __float2bfloat16(v.x - __bfloat162float(h0));
    __nv_bfloat16 a1 = __float2bfloat16(v.y - __bfloat162float(h1));
    __nv_bfloat16 a2 = __float2bfloat16(v.z - __bfloat162float(h2));
    __nv_bfloat16 a3 = __float2bfloat16(v.w - __bfloat162float(h3));
    h.x = (uint32_t)__bfloat16_as_ushort(h0) | ((uint32_t)__bfloat16_as_ushort(h1) << 16);
    h.y = (uint32_t)__bfloat16_as_ushort(h2) | ((uint32_t)__bfloat16_as_ushort(h3) << 16);
    l.x = (uint32_t)__bfloat16_as_ushort(a0) | ((uint32_t)__bfloat16_as_ushort(a1) << 16);
    l.y = (uint32_t)__bfloat16_as_ushort(a2) | ((uint32_t)__bfloat16_as_ushort(a3) << 16);
}

// ---------------- small kernels ----------------------------------------------
__global__ void init_kernel() {
    int i = blockIdx.x * blockDim.x + threadIdx.x;
    if (i < NROW) { g_rowsum[i] = 0.f; g_rowsq[i] = 0.f; }
}

__global__ void mask_kernel(const float* __restrict__ tgt,
                            const float* __restrict__ src) {
    int rb = blockIdx.x;
    const float* p;
    float* dst;
    if (rb < NROW) { p = tgt + (size_t)rb * Dd; dst = &g_tgtmask[rb]; }
    else           { p = src + (size_t)(rb - NROW) * Dd; dst = &g_srcmask[rb - NROW]; }
    float s = 0.f;
    for (int i = threadIdx.x; i < Dd; i += 128) s += fabsf(p[i]);
    s = warp_sum(s);
    __shared__ float sc[4];
    if ((threadIdx.x & 31) == 0) sc[threadIdx.x >> 5] = s;
    __syncthreads();
    if (threadIdx.x == 0)
        *dst = ((sc[0] + sc[1] + sc[2] + sc[3]) > 0.f) ? 1.f : 0.f;
}

// ---------------- split-bf16 mma.sync GEMM (fp32 in, in-kernel split) --------
// C[m,n] = sum_k A[m,k]*B[n,k] + bias[n]; A,B fp32 row-major (NT).
// CTA tile 128x128, BK=16, 128 threads = 4 warps (2M x 2N), warp tile 64x64.
// SMEM layout: per tile 128 rows, pitch 80B, payload 2x16B chunks placed at
// slot ((row>>3)+chunk)%5 -> conflict-free STS (1 thread/row) and LDSM.
// Prefetch-1 in regs; 2 CTAs/SM hide the latency.
#define PITCH 80
#define TILE_BYTES (128 * PITCH)     // 10240
#define T_AHI 0
#define T_ALO TILE_BYTES
#define T_BHI (2 * TILE_BYTES)
#define T_BLO (3 * TILE_BYTES)
#define STAGE_BYTES (4 * TILE_BYTES) // 40960
#define GEMM_SMEM (2 * STAGE_BYTES)  // 81920
#define KSTEPS (Dd / 16)             // 32

__device__ __forceinline__ void gemm_core(
    const float* __restrict__ A, int lda,
    const float* __restrict__ B, int ldb,
    const float* __restrict__ bias,
    float* __restrict__ C, int ldc, int do_stats,
    size_t m0, size_t n0, uint8_t* smem_raw) {
    uint32_t smb = smem_u32(smem_raw);

    int tid = threadIdx.x, wid = tid >> 5, lane = tid & 31;
    int warp_m = wid >> 1, warp_n = wid & 1;

    // loader: thread t owns row t of both A and B tiles (full k16 row = 4 f4)
    const float* aptr = A + (m0 + (size_t)tid) * (size_t)lda;
    const float* bptr = B + (n0 + (size_t)tid) * (size_t)ldb;
    uint32_t o0 = (uint32_t)(PITCH * tid + 16 * ((tid >> 3) % 5));
    uint32_t o1 = (uint32_t)(PITCH * tid + 16 * (((tid >> 3) + 1) % 5));

    // ldmatrix per-lane offsets (loop-invariant)
    int q = lane >> 3, li = lane & 7;
    uint32_t aof[4], bof[4];
#pragma unroll
    for (int mt = 0; mt < 4; mt++) {
        int r = warp_m * 64 + mt * 16 + (q & 1) * 8 + li;
        aof[mt] = (uint32_t)(PITCH * r + 16 * (((r >> 3) + (q >> 1)) % 5));
    }
#pragma unroll
    for (int c = 0; c < 4; c++) {
        int r = warp_n * 64 + c * 16 + (q >> 1) * 8 + li;
        bof[c] = (uint32_t)(PITCH * r + 16 * (((r >> 3) + (q & 1)) % 5));
    }

    F4 d[4][8];
#pragma unroll
    for (int mt = 0; mt < 4; mt++)
#pragma unroll
        for (int nt = 0; nt < 8; nt++) {
            d[mt][nt].x = 0.f; d[mt][nt].y = 0.f;
            d[mt][nt].z = 0.f; d[mt][nt].w = 0.f;
        }

    // prefetch k-step 0
    float4 pa0 = *(const float4*)(aptr + 0);
    float4 pa1 = *(const float4*)(aptr + 4);
    float4 pa2 = *(const float4*)(aptr + 8);
    float4 pa3 = *(const float4*)(aptr + 12);
    float4 pb0 = *(const float4*)(bptr + 0);
    float4 pb1 = *(const float4*)(bptr + 4);
    float4 pb2 = *(const float4*)(bptr + 8);
    float4 pb3 = *(const float4*)(bptr + 12);

#pragma unroll 1
    for (int s = 0; s < KSTEPS; s++) {
        uint32_t SB = smb + (uint32_t)((s & 1) * STAGE_BYTES);
        // STS current step (split fp32 -> bf16 hi/lo)
        {
            uint2 h0, l0, h1, l1, h2, l2, h3, l3;
            split4(pa0, h0, l0); split4(pa1, h1, l1);
            split4(pa2, h2, l2); split4(pa3, h3, l3);
            sts16(SB + T_AHI + o0, h0.x, h0.y, h1.x, h1.y);
            sts16(SB + T_AHI + o1, h2.x, h2.y, h3.x, h3.y);
            sts16(SB + T_ALO + o0, l0.x, l0.y, l1.x, l1.y);
            sts16(SB + T_ALO + o1, l2.x, l2.y, l3.x, l3.y);
            split4(pb0, h0, l0); split4(pb1, h1, l1);
            split4(pb2, h2, l2); split4(pb3, h3, l3);
            sts16(SB + T_BHI + o0, h0.x, h0.y, h1.x, h1.y);
            sts16(SB + T_BHI + o1, h2.x, h2.y, h3.x, h3.y);
            sts16(SB + T_BLO + o0, l0.x, l0.y, l1.x, l1.y);
            sts16(SB + T_BLO + o1, l2.x, l2.y, l3.x, l3.y);
        }
        // LDG next step (in flight during MMA phase)
        if (s + 1 < KSTEPS) {
            int k = (s + 1) * 16;
            pa0 = *(const float4*)(aptr + k);
            pa1 = *(const float4*)(aptr + k + 4);
            pa2 = *(const float4*)(aptr + k + 8);
            pa3 = *(const float4*)(aptr + k + 12);
            pb0 = *(const float4*)(bptr + k);
            pb1 = *(const float4*)(bptr + k + 4);
            pb2 = *(const float4*)(bptr + k + 8);
            pb3 = *(const float4*)(bptr + k + 12);
        }
        __syncthreads();

        // MMA phase: 8 A-frag LDSM + 8 B-frag LDSM + 96 MMAs per warp
        U4 ah[4], al[4];
#pragma unroll
        for (int mt = 0; mt < 4; mt++) {
            ah[mt] = ldmx4(SB + T_AHI + aof[mt]);
            al[mt] = ldmx4(SB + T_ALO + aof[mt]);
        }
#pragma unroll
        for (int c = 0; c < 4; c++) {
            U4 b = ldmx4(SB + T_BHI + bof[c]);
#pragma unroll
            for (int mt = 0; mt < 4; mt++) {
                mma(d[mt][2 * c + 0], ah[mt], b.x, b.y);
                mma(d[mt][2 * c + 1], ah[mt], b.z, b.w);
                mma(d[mt][2 * c + 0], al[mt], b.x, b.y);
                mma(d[mt][2 * c + 1], al[mt], b.z, b.w);
            }
            b = ldmx4(SB + T_BLO + bof[c]);
#pragma unroll
            for (int mt = 0; mt < 4; mt++) {
                mma(d[mt][2 * c + 0], ah[mt], b.x, b.y);
                mma(d[mt][2 * c + 1], ah[mt], b.z, b.w);
            }
        }
    }

    // epilogue
    int groupl = lane >> 2, subl = lane & 3;
    int colbase = (int)n0 + warp_n * 64 + subl * 2;

#pragma unroll
    for (int mt = 0; mt < 4; mt++) {
#pragma unroll
        for (int half = 0; half < 2; half++) {
            size_t r = m0 + (size_t)(warp_m * 64 + mt * 16 + half * 8 + groupl);
            float* crow = C + r * (size_t)ldc + colbase;
            float ssum = 0.f, sq = 0.f;
#pragma unroll
            for (int nt = 0; nt < 8; nt++) {
                float v0 = half ? d[mt][nt].z : d[mt][nt].x;
                float v1 = half ? d[mt][nt].w : d[mt][nt].y;
                if (bias) {
                    v0 += __ldg(bias + colbase + nt * 8);
                    v1 += __ldg(bias + colbase + nt * 8 + 1);
                }
                *(float2*)(crow + nt * 8) = make_float2(v0, v1);
                ssum += v0 + v1;
                sq += fmaf(v0, v0, v1 * v1);
            }
            if (do_stats) {
                ssum += __shfl_xor_sync(0xffffffffu, ssum, 1);
                ssum += __shfl_xor_sync(0xffffffffu, ssum, 2);
                sq   += __shfl_xor_sync(0xffffffffu, sq, 1);
                sq   += __shfl_xor_sync(0xffffffffu, sq, 2);
                if (subl == 0) {
                    atomicAdd(&g_rowsum[r], ssum);
                    atomicAdd(&g_rowsq[r], sq);
                }
            }
        }
    }
}

// logits GEMM (generic)
__global__ __launch_bounds__(128, 2)
void mma_gemm(const float* __restrict__ A, int lda,
              const float* __restrict__ B, int ldb,
              const float* __restrict__ bias,
              float* __restrict__ C, int ldc, int do_stats) {
    extern __shared__ __align__(16) uint8_t smbuf[];
    gemm_core(A, lda, B, ldb, bias, C, ldc, do_stats,
              (size_t)blockIdx.y * 128, (size_t)blockIdx.x * 128, smbuf);
}

// merged qproj + kproj: z=0 -> qproj (4 M-blocks of 128), z=1 -> kproj (8)
__global__ __launch_bounds__(128, 2)
void qk_gemm(const float* __restrict__ tgt, const float* __restrict__ src,
             const float* __restrict__ W_attn, const float* __restrict__ b_attn) {
    extern __shared__ __align__(16) uint8_t smbuf[];
    if (blockIdx.z == 0) {
        if (blockIdx.y >= NROW / 128) return;
        gemm_core(tgt, Dd, W_attn, 2 * Dd, b_attn, g_qproj, Dd, 0,
                  (size_t)blockIdx.y * 128, (size_t)blockIdx.x * 128, smbuf);
    } else {
        gemm_core(src, Dd, W_attn + Dd, 2 * Dd, nullptr, g_kproj, Dd, 0,
                  (size_t)blockIdx.y * 128, (size_t)blockIdx.x * 128, smbuf);
    }
}

// ---------------- fused additive attention -----------------------------------
__global__ __launch_bounds__(256)
void attn_kernel(const float* __restrict__ src, const float* __restrict__ v_w,
                 const float* __restrict__ W_lin, const float* __restrict__ b_lin) {
    __shared__ float qp[Dd];
    __shared__ float vw[Dd];
    __shared__ float sraw[TK];
    __shared__ float sprob[TK];
    __shared__ float scr[9];

    int row = blockIdx.x;
    int b = row >> 6;
    int tid = threadIdx.x, lane = tid & 31, w = tid >> 5;

    for (int i = tid; i < Dd; i += 256) {
        qp[i] = g_qproj[row * Dd + i];
        vw[i] = v_w[i];
    }
    float tm = g_tgtmask[row];
    __syncthreads();

    float qpr[16], vwr[16];
#pragma unroll
    for (int j = 0; j < 16; j++) {
        qpr[j] = qp[lane + 32 * j];
        vwr[j] = vw[lane + 32 * j];
    }

    for (int k = w; k < TK; k += 8) {
        const float* kp = g_kproj + ((size_t)(b * TK + k)) * Dd;
        float acc = 0.f;
#pragma unroll
        for (int j = 0; j < 16; j++)
            acc += tanh_fast(qpr[j] + __ldg(kp + lane + 32 * j)) * vwr[j];
        acc = warp_sum(acc);
        if (lane == 0) sraw[k] = acc;
    }
    __syncthreads();

    float raw = 0.f, smk = 0.f;
    if (tid < TK) { raw = sraw[tid]; smk = g_srcmask[b * TK + tid]; }
    float masked = (tid < TK) ? ((smk == 0.f) ? -1e30f : raw) : -1e30f;
    float mx = block_max256(masked, scr);
    float e = (tid < TK) ? __expf(masked - mx) : 0.f;
    float ssum = block_sum256(e, scr);
    if (tid < TK) sprob[tid] = e / ssum;

    float oa = (tid < TK) ? raw * smk * tm : 0.f;
    float osum = block_sum256(oa, scr);
    float osq  = block_sum256(oa * oa, scr);

    float zacc = 0.f;
    for (int dd = tid; dd < Dd; dd += 256) {
        float wv = 0.f;
        const float* sp = src + ((size_t)b * TK) * Dd + dd;
#pragma unroll 4
        for (int k = 0; k < TK; k++) wv = fmaf(sprob[k], sp[(size_t)k * Dd], wv);
        wv *= tm;
        zacc = fmaf(wv, W_lin[dd], zacc);
    }
    float z = block_sum256(zacc, scr);
    if (tid == 0) g_p[row] = 1.f / (1.f + __expf(-(z + b_lin[0])));

    float mean = osum * (1.f / (float)TK);
    float var = osq * (1.f / (float)TK) - mean * mean;
    float inv = rsqrtf(var + 1e-5f);
    if (tid < TK) g_att[row * TK + tid] = (oa - mean) * inv;
}

// ---------------- combine (in-place on out) + scatter -------------------------
__global__ __launch_bounds__(256)
void combine_kernel(float* __restrict__ out) {
    int row = blockIdx.x;
    float mean = g_rowsum[row] * (1.f / (float)Vv);
    float var = g_rowsq[row] * (1.f / (float)Vv) - mean * mean;
    float inv = rsqrtf(var + 1e-5f);
    float pv = g_p[row];
    float a = inv * pv;
    float c = -mean * inv * pv;
    float4* op = (float4*)(out + (size_t)row * EXTN);
    for (int i = threadIdx.x; i < Vv / 4; i += 256) {
        float4 v = op[i];
        v.x = fmaf(v.x, a, c); v.y = fmaf(v.y, a, c);
        v.z = fmaf(v.z, a, c); v.w = fmaf(v.w, a, c);
        op[i] = v;
    }
    for (int j = Vv + threadIdx.x; j < EXTN; j += 256)
        out[(size_t)row * EXTN + j] = 0.f;
}

// src_map_idx is int32 on the wire (JAX x64-disabled); bounds-guarded.
__global__ void scatter_kernel(float* __restrict__ out,
                               const int* __restrict__ map) {
    int row = blockIdx.x;
    int b = row >> 6;
    float q = 1.f - g_p[row];
    for (int k = threadIdx.x; k < TK; k += blockDim.x) {
        int idx = map[b * TK + k];
        if (idx >= 0 && idx < EXTN)
            atomicAdd(out + (size_t)row * EXTN + (size_t)idx,
                      q * g_att[row * TK + k]);
    }
}

// ---------------- launch ------------------------------------------------------
extern "C" void kernel_launch(void* const* d_in, const int* in_sizes, int n_in,
                              void* d_out, int out_size) {
    const float* tgt    = (const float*)d_in[0];
    const float* src    = (const float*)d_in[1];
    const int*   mp     = (const int*)d_in[2];
    const float* W_out  = (const float*)d_in[3];
    const float* b_out  = (const float*)d_in[4];
    const float* W_attn = (const float*)d_in[5];
    const float* b_attn = (const float*)d_in[6];
    const float* v_w    = (const float*)d_in[7];
    const float* W_lin  = (const float*)d_in[8];
    const float* b_lin  = (const float*)d_in[9];
    float* out = (float*)d_out;

    static int attr_set = 0;
    if (!attr_set) {
        cudaFuncSetAttribute(mma_gemm, cudaFuncAttributeMaxDynamicSharedMemorySize,
                             GEMM_SMEM);
        cudaFuncSetAttribute(qk_gemm, cudaFuncAttributeMaxDynamicSharedMemorySize,
                             GEMM_SMEM);
        attr_set = 1;
    }

    init_kernel<<<2, 256>>>();
    mask_kernel<<<NROW + NKROW, 128>>>(tgt, src);

    // qproj + kproj merged (z=0: qproj 4 M-blocks; z=1: kproj 8 M-blocks)
    qk_gemm<<<dim3(Dd / 128, NKROW / 128, 2), 128, GEMM_SMEM>>>(
        tgt, src, W_attn, b_attn);

    // logits = tgt @ W_out^T + b_out, written straight into out (ldc = EXTN)
    mma_gemm<<<dim3(Vv / 128, NROW / 128), 128, GEMM_SMEM>>>(
        tgt, Dd, W_out, Dd, b_out, out, EXTN, 1);

    attn_kernel<<<NROW, 256>>>(src, v_w, W_lin, b_lin);
    combine_kernel<<<NROW, 256>>>(out);
    scatter_kernel<<<NROW, 128>>>(out, mp);
}

// round 12
// speedup vs baseline: 1.0736x; 1.0736x over previous
#include <cuda_runtime.h>
#include <cuda_bf16.h>
#include <cuda_fp16.h>
#include <cstdint>

// Problem constants
#define Bz   8
#define TQ   64
#define TK   128
#define Dd   512
#define Vv   32000
#define EXTN (Vv + TK)      // 32128
#define NROW (Bz * TQ)      // 512
#define NKROW (Bz * TK)     // 1024

// ---------------- scratch (device globals; ~3.3 MB total) --------------------
__device__ float g_qproj[NROW * Dd];
__device__ float g_kproj[NKROW * Dd];
__device__ float g_att[NROW * TK];
__device__ float g_p[NROW];
__device__ float g_rowsum[NROW];
__device__ float g_rowsq[NROW];
__device__ float g_srcmask[NKROW];
__device__ float g_tgtmask[NROW];

// ---------------- generic helpers -------------------------------------------
__device__ __forceinline__ float warp_sum(float v) {
#pragma unroll
    for (int o = 16; o > 0; o >>= 1) v += __shfl_xor_sync(0xffffffffu, v, o);
    return v;
}
__device__ __forceinline__ float warp_max(float v) {
#pragma unroll
    for (int o = 16; o > 0; o >>= 1) v = fmaxf(v, __shfl_xor_sync(0xffffffffu, v, o));
    return v;
}
__device__ __forceinline__ float block_sum256(float v, float* scr) {
    v = warp_sum(v);
    int w = threadIdx.x >> 5;
    __syncthreads();
    if ((threadIdx.x & 31) == 0) scr[w] = v;
    __syncthreads();
    if (threadIdx.x == 0) {
        float t = 0.f;
#pragma unroll
        for (int i = 0; i < 8; i++) t += scr[i];
        scr[8] = t;
    }
    __syncthreads();
    return scr[8];
}
__device__ __forceinline__ float block_max256(float v, float* scr) {
    v = warp_max(v);
    int w = threadIdx.x >> 5;
    __syncthreads();
    if ((threadIdx.x & 31) == 0) scr[w] = v;
    __syncthreads();
    if (threadIdx.x == 0) {
        float t = scr[0];
#pragma unroll
        for (int i = 1; i < 8; i++) t = fmaxf(t, scr[i]);
        scr[8] = t;
    }
    __syncthreads();
    return scr[8];
}

// FMA-only tanh (proven; MUFU tanh would be throughput-bound at 33.5M calls)
__device__ __forceinline__ float tanh_fast(float x) {
    float z = x * 2.885390081777927f;             // 2x * log2(e)
    z = fminf(25.f, fmaxf(-25.f, z));
    const float big = 12582912.f;                 // 1.5 * 2^23
    float t  = z + big;
    float nf = t - big;
    float f  = z - nf;
    int   n  = __float_as_int(t) - 0x4B400000;
    float p = 1.33335581e-3f;
    p = fmaf(p, f, 9.61804886e-3f);
    p = fmaf(p, f, 5.55041087e-2f);
    p = fmaf(p, f, 2.40226337e-1f);
    p = fmaf(p, f, 6.93147182e-1f);
    p = fmaf(p, f, 1.0f);
    float y = __int_as_float(__float_as_int(p) + (n << 23));  // e^{2x}
    float d = y + 1.f;
    float r = __int_as_float((int)(0x7EF127EAu - (unsigned)__float_as_int(d)));
    r = r * fmaf(-d, r, 2.f);
    r = r * fmaf(-d, r, 2.f);
    r = r * fmaf(-d, r, 2.f);
    return (y - 1.f) * r;
}
__device__ __forceinline__ uint32_t smem_u32(const void* p) {
    uint32_t a;
    asm("{ .reg .u64 t; cvta.to.shared.u64 t, %1; cvt.u32.u64 %0, t; }"
        : "=r"(a) : "l"(p));
    return a;
}

// value-only fragment types
struct U4 { uint32_t x, y, z, w; };
struct F4 { float x, y, z, w; };

__device__ __forceinline__ U4 ldmx4(uint32_t addr) {
    U4 r;
    asm volatile("ldmatrix.sync.aligned.m8n8.x4.shared.b16 {%0,%1,%2,%3}, [%4];"
                 : "=r"(r.x), "=r"(r.y), "=r"(r.z), "=r"(r.w) : "r"(addr));
    return r;
}
__device__ __forceinline__ void mma(F4& d, const U4& a, uint32_t b0, uint32_t b1) {
    asm volatile("mma.sync.aligned.m16n8k16.row.col.f32.f16.f16.f32 "
        "{%0,%1,%2,%3}, {%4,%5,%6,%7}, {%8,%9}, {%0,%1,%2,%3};"
        : "+f"(d.x), "+f"(d.y), "+f"(d.z), "+f"(d.w)
        : "r"(a.x), "r"(a.y), "r"(a.z), "r"(a.w), "r"(b0), "r"(b1));
}
__device__ __forceinline__ void sts16(uint32_t addr, uint32_t v0, uint32_t v1,
                                      uint32_t v2, uint32_t v3) {
    asm volatile("st.shared.v4.u32 [%0], {%1, %2, %3, %4};"
                 :: "r"(addr), "r"(v0), "r"(v1), "r"(v2), "r"(v3));
}

// A: fp32x4 -> packed fp16x2 (round-to-nearest; hi only)
__device__ __forceinline__ void cvtA4(float4 v, uint2& h) {
    h.x = (uint32_t)__half_as_ushort(__float2half_rn(v.x))
        | ((uint32_t)__half_as_ushort(__float2half_rn(v.y)) << 16);
    h.y = (uint32_t)__half_as_ushort(__float2half_rn(v.z))
        | ((uint32_t)__half_as_ushort(__float2half_rn(v.w)) << 16);
}
// B: scale by 32 (keeps lo out of fp16-denormal range), split hi/lo
#define BSCALE 32.0f
#define BINV   0.03125f
__device__ __forceinline__ void splitB4(float4 v, uint2& h, uint2& l) {
    v.x *= BSCALE; v.y *= BSCALE; v.z *= BSCALE; v.w *= BSCALE;
    __half h0 = __float2half_rn(v.x), h1 = __float2half_rn(v.y);
    __half h2 = __float2half_rn(v.z), h3 = __float2half_rn(v.w);
    __half a0 = __float2half_rn(v.x - __half2float(h0));
    __half a1 = __float2half_rn(v.y - __half2float(h1));
    __half a2 = __float2half_rn(v.z - __half2float(h2));
    __half a3 = __float2half_rn(v.w - __half2float(h3));
    h.x = (uint32_t)__half_as_ushort(h0) | ((uint32_t)__half_as_ushort(h1) << 16);
    h.y = (uint32_t)__half_as_ushort(h2) | ((uint32_t)__half_as_ushort(h3) << 16);
    l.x = (uint32_t)__half_as_ushort(a0) | ((uint32_t)__half_as_ushort(a1) << 16);
    l.y = (uint32_t)__half_as_ushort(a2) | ((uint32_t)__half_as_ushort(a3) << 16);
}

// ---------------- small kernels ----------------------------------------------
__global__ void init_kernel() {
    int i = blockIdx.x * blockDim.x + threadIdx.x;
    if (i < NROW) { g_rowsum[i] = 0.f; g_rowsq[i] = 0.f; }
}

__global__ void mask_kernel(const float* __restrict__ tgt,
                            const float* __restrict__ src) {
    int rb = blockIdx.x;
    const float* p;
    float* dst;
    if (rb < NROW) { p = tgt + (size_t)rb * Dd; dst = &g_tgtmask[rb]; }
    else           { p = src + (size_t)(rb - NROW) * Dd; dst = &g_srcmask[rb - NROW]; }
    float s = 0.f;
    for (int i = threadIdx.x; i < Dd; i += 128) s += fabsf(p[i]);
    s = warp_sum(s);
    __shared__ float sc[4];
    if ((threadIdx.x & 31) == 0) sc[threadIdx.x >> 5] = s;
    __syncthreads();
    if (threadIdx.x == 0)
        *dst = ((sc[0] + sc[1] + sc[2] + sc[3]) > 0.f) ? 1.f : 0.f;
}

// ---------------- fp16 2-product mma.sync GEMM (fp32 in, in-kernel cvt) ------
// C[m,n] = sum_k A[m,k]*B[n,k] + bias[n]; A,B fp32 row-major (NT).
// A -> fp16 (hi only); B -> 32*B split into fp16 hi+lo.
// D = A_hi*B_hi + A_hi*B_lo, scaled by 1/32 in epilogue. err ~2^-12.
// CTA tile 128x128, BK=16, 128 threads = 4 warps (2M x 2N), warp tile 64x64.
// SMEM: 3 tiles (AHI, BHI, BLO), pitch 80B, slot rotation -> conflict-free.
#define PITCH 80
#define TILE_BYTES (128 * PITCH)     // 10240
#define T_AHI 0
#define T_BHI TILE_BYTES
#define T_BLO (2 * TILE_BYTES)
#define STAGE_BYTES (3 * TILE_BYTES) // 30720
#define GEMM_SMEM (2 * STAGE_BYTES)  // 61440
#define KSTEPS (Dd / 16)             // 32

__device__ __forceinline__ void gemm_core(
    const float* __restrict__ A, int lda,
    const float* __restrict__ B, int ldb,
    const float* __restrict__ bias,
    float* __restrict__ C, int ldc, int do_stats,
    size_t m0, size_t n0, uint8_t* smem_raw) {
    uint32_t smb = smem_u32(smem_raw);

    int tid = threadIdx.x, wid = tid >> 5, lane = tid & 31;
    int warp_m = wid >> 1, warp_n = wid & 1;

    // loader: thread t owns row t of both A and B tiles (full k16 row)
    const float* aptr = A + (m0 + (size_t)tid) * (size_t)lda;
    const float* bptr = B + (n0 + (size_t)tid) * (size_t)ldb;
    uint32_t o0 = (uint32_t)(PITCH * tid + 16 * ((tid >> 3) % 5));
    uint32_t o1 = (uint32_t)(PITCH * tid + 16 * (((tid >> 3) + 1) % 5));

    // ldmatrix per-lane offsets (loop-invariant)
    int q = lane >> 3, li = lane & 7;
    uint32_t aof[4], bof[4];
#pragma unroll
    for (int mt = 0; mt < 4; mt++) {
        int r = warp_m * 64 + mt * 16 + (q & 1) * 8 + li;
        aof[mt] = (uint32_t)(PITCH * r + 16 * (((r >> 3) + (q >> 1)) % 5));
    }
#pragma unroll
    for (int c = 0; c < 4; c++) {
        int r = warp_n * 64 + c * 16 + (q >> 1) * 8 + li;
        bof[c] = (uint32_t)(PITCH * r + 16 * (((r >> 3) + (q & 1)) % 5));
    }

    F4 d[4][8];
#pragma unroll
    for (int mt = 0; mt < 4; mt++)
#pragma unroll
        for (int nt = 0; nt < 8; nt++) {
            d[mt][nt].x = 0.f; d[mt][nt].y = 0.f;
            d[mt][nt].z = 0.f; d[mt][nt].w = 0.f;
        }

    // prefetch k-step 0
    float4 pa0 = *(const float4*)(aptr + 0);
    float4 pa1 = *(const float4*)(aptr + 4);
    float4 pa2 = *(const float4*)(aptr + 8);
    float4 pa3 = *(const float4*)(aptr + 12);
    float4 pb0 = *(const float4*)(bptr + 0);
    float4 pb1 = *(const float4*)(bptr + 4);
    float4 pb2 = *(const float4*)(bptr + 8);
    float4 pb3 = *(const float4*)(bptr + 12);

#pragma unroll 1
    for (int s = 0; s < KSTEPS; s++) {
        uint32_t SB = smb + (uint32_t)((s & 1) * STAGE_BYTES);
        // STS current step
        {
            uint2 ha0, ha1, ha2, ha3;
            cvtA4(pa0, ha0); cvtA4(pa1, ha1); cvtA4(pa2, ha2); cvtA4(pa3, ha3);
            sts16(SB + T_AHI + o0, ha0.x, ha0.y, ha1.x, ha1.y);
            sts16(SB + T_AHI + o1, ha2.x, ha2.y, ha3.x, ha3.y);
            uint2 h0, l0, h1, l1, h2, l2, h3, l3;
            splitB4(pb0, h0, l0); splitB4(pb1, h1, l1);
            splitB4(pb2, h2, l2); splitB4(pb3, h3, l3);
            sts16(SB + T_BHI + o0, h0.x, h0.y, h1.x, h1.y);
            sts16(SB + T_BHI + o1, h2.x, h2.y, h3.x, h3.y);
            sts16(SB + T_BLO + o0, l0.x, l0.y, l1.x, l1.y);
            sts16(SB + T_BLO + o1, l2.x, l2.y, l3.x, l3.y);
        }
        // LDG next step (in flight during MMA phase)
        if (s + 1 < KSTEPS) {
            int k = (s + 1) * 16;
            pa0 = *(const float4*)(aptr + k);
            pa1 = *(const float4*)(aptr + k + 4);
            pa2 = *(const float4*)(aptr + k + 8);
            pa3 = *(const float4*)(aptr + k + 12);
            pb0 = *(const float4*)(bptr + k);
            pb1 = *(const float4*)(bptr + k + 4);
            pb2 = *(const float4*)(bptr + k + 8);
            pb3 = *(const float4*)(bptr + k + 12);
        }
        __syncthreads();

        // MMA phase: 4 A LDSM + 8 B LDSM + 64 MMAs per warp,
        // B-hi prefetched one c ahead to cover LDSM latency.
        U4 ah0 = ldmx4(SB + T_AHI + aof[0]);
        U4 ah1 = ldmx4(SB + T_AHI + aof[1]);
        U4 ah2 = ldmx4(SB + T_AHI + aof[2]);
        U4 ah3 = ldmx4(SB + T_AHI + aof[3]);
        U4 bh = ldmx4(SB + T_BHI + bof[0]);
#pragma unroll
        for (int c = 0; c < 4; c++) {
            U4 bl = ldmx4(SB + T_BLO + bof[c]);
            U4 bhn;
            if (c < 3) bhn = ldmx4(SB + T_BHI + bof[c + 1]);
            mma(d[0][2 * c], ah0, bh.x, bh.y); mma(d[0][2 * c + 1], ah0, bh.z, bh.w);
            mma(d[1][2 * c], ah1, bh.x, bh.y); mma(d[1][2 * c + 1], ah1, bh.z, bh.w);
            mma(d[2][2 * c], ah2, bh.x, bh.y); mma(d[2][2 * c + 1], ah2, bh.z, bh.w);
            mma(d[3][2 * c], ah3, bh.x, bh.y); mma(d[3][2 * c + 1], ah3, bh.z, bh.w);
            mma(d[0][2 * c], ah0, bl.x, bl.y); mma(d[0][2 * c + 1], ah0, bl.z, bl.w);
            mma(d[1][2 * c], ah1, bl.x, bl.y); mma(d[1][2 * c + 1], ah1, bl.z, bl.w);
            mma(d[2][2 * c], ah2, bl.x, bl.y); mma(d[2][2 * c + 1], ah2, bl.z, bl.w);
            mma(d[3][2 * c], ah3, bl.x, bl.y); mma(d[3][2 * c + 1], ah3, bl.z, bl.w);
            bh = bhn;
        }
    }

    // epilogue (accumulators carry the 32x B scale; undo with BINV)
    int groupl = lane >> 2, subl = lane & 3;
    int colbase = (int)n0 + warp_n * 64 + subl * 2;

#pragma unroll
    for (int mt = 0; mt < 4; mt++) {
#pragma unroll
        for (int half = 0; half < 2; half++) {
            size_t r = m0 + (size_t)(warp_m * 64 + mt * 16 + half * 8 + groupl);
            float* crow = C + r * (size_t)ldc + colbase;
            float ssum = 0.f, sq = 0.f;
#pragma unroll
            for (int nt = 0; nt < 8; nt++) {
                float v0 = (half ? d[mt][nt].z : d[mt][nt].x) * BINV;
                float v1 = (half ? d[mt][nt].w : d[mt][nt].y) * BINV;
                if (bias) {
                    v0 += __ldg(bias + colbase + nt * 8);
                    v1 += __ldg(bias + colbase + nt * 8 + 1);
                }
                *(float2*)(crow + nt * 8) = make_float2(v0, v1);
                ssum += v0 + v1;
                sq += fmaf(v0, v0, v1 * v1);
            }
            if (do_stats) {
                ssum += __shfl_xor_sync(0xffffffffu, ssum, 1);
                ssum += __shfl_xor_sync(0xffffffffu, ssum, 2);
                sq   += __shfl_xor_sync(0xffffffffu, sq, 1);
                sq   += __shfl_xor_sync(0xffffffffu, sq, 2);
                if (subl == 0) {
                    atomicAdd(&g_rowsum[r], ssum);
                    atomicAdd(&g_rowsq[r], sq);
                }
            }
        }
    }
}

// logits GEMM (generic)
__global__ __launch_bounds__(128, 2)
void mma_gemm(const float* __restrict__ A, int lda,
              const float* __restrict__ B, int ldb,
              const float* __restrict__ bias,
              float* __restrict__ C, int ldc, int do_stats) {
    extern __shared__ __align__(16) uint8_t smbuf[];
    gemm_core(A, lda, B, ldb, bias, C, ldc, do_stats,
              (size_t)blockIdx.y * 128, (size_t)blockIdx.x * 128, smbuf);
}

// merged qproj + kproj: z=0 -> qproj (4 M-blocks of 128), z=1 -> kproj (8)
__global__ __launch_bounds__(128, 2)
void qk_gemm(const float* __restrict__ tgt, const float* __restrict__ src,
             const float* __restrict__ W_attn, const float* __restrict__ b_attn) {
    extern __shared__ __align__(16) uint8_t smbuf[];
    if (blockIdx.z == 0) {
        if (blockIdx.y >= NROW / 128) return;
        gemm_core(tgt, Dd, W_attn, 2 * Dd, b_attn, g_qproj, Dd, 0,
                  (size_t)blockIdx.y * 128, (size_t)blockIdx.x * 128, smbuf);
    } else {
        gemm_core(src, Dd, W_attn + Dd, 2 * Dd, nullptr, g_kproj, Dd, 0,
                  (size_t)blockIdx.y * 128, (size_t)blockIdx.x * 128, smbuf);
    }
}

// ---------------- fused additive attention -----------------------------------
__global__ __launch_bounds__(256)
void attn_kernel(const float* __restrict__ src, const float* __restrict__ v_w,
                 const float* __restrict__ W_lin, const float* __restrict__ b_lin) {
    __shared__ float qp[Dd];
    __shared__ float vw[Dd];
    __shared__ float sraw[TK];
    __shared__ float sprob[TK];
    __shared__ float scr[9];

    int row = blockIdx.x;
    int b = row >> 6;
    int tid = threadIdx.x, lane = tid & 31, w = tid >> 5;

    for (int i = tid; i < Dd; i += 256) {
        qp[i] = g_qproj[row * Dd + i];
        vw[i] = v_w[i];
    }
    float tm = g_tgtmask[row];
    __syncthreads();

    float qpr[16], vwr[16];
#pragma unroll
    for (int j = 0; j < 16; j++) {
        qpr[j] = qp[lane + 32 * j];
        vwr[j] = vw[lane + 32 * j];
    }

    for (int k = w; k < TK; k += 8) {
        const float* kp = g_kproj + ((size_t)(b * TK + k)) * Dd;
        float acc = 0.f;
#pragma unroll
        for (int j = 0; j < 16; j++)
            acc += tanh_fast(qpr[j] + __ldg(kp + lane + 32 * j)) * vwr[j];
        acc = warp_sum(acc);
        if (lane == 0) sraw[k] = acc;
    }
    __syncthreads();

    float raw = 0.f, smk = 0.f;
    if (tid < TK) { raw = sraw[tid]; smk = g_srcmask[b * TK + tid]; }
    float masked = (tid < TK) ? ((smk == 0.f) ? -1e30f : raw) : -1e30f;
    float mx = block_max256(masked, scr);
    float e = (tid < TK) ? __expf(masked - mx) : 0.f;
    float ssum = block_sum256(e, scr);
    if (tid < TK) sprob[tid] = e / ssum;

    float oa = (tid < TK) ? raw * smk * tm : 0.f;
    float osum = block_sum256(oa, scr);
    float osq  = block_sum256(oa * oa, scr);

    float zacc = 0.f;
    for (int dd = tid; dd < Dd; dd += 256) {
        float wv = 0.f;
        const float* sp = src + ((size_t)b * TK) * Dd + dd;
#pragma unroll 4
        for (int k = 0; k < TK; k++) wv = fmaf(sprob[k], sp[(size_t)k * Dd], wv);
        wv *= tm;
        zacc = fmaf(wv, W_lin[dd], zacc);
    }
    float z = block_sum256(zacc, scr);
    if (tid == 0) g_p[row] = 1.f / (1.f + __expf(-(z + b_lin[0])));

    float mean = osum * (1.f / (float)TK);
    float var = osq * (1.f / (float)TK) - mean * mean;
    float inv = rsqrtf(var + 1e-5f);
    if (tid < TK) g_att[row * TK + tid] = (oa - mean) * inv;
}

// ---------------- combine (in-place on out) + scatter -------------------------
__global__ __launch_bounds__(256)
void combine_kernel(float* __restrict__ out) {
    int row = blockIdx.x;
    float mean = g_rowsum[row] * (1.f / (float)Vv);
    float var = g_rowsq[row] * (1.f / (float)Vv) - mean * mean;
    float inv = rsqrtf(var + 1e-5f);
    float pv = g_p[row];
    float a = inv * pv;
    float c = -mean * inv * pv;
    float4* op = (float4*)(out + (size_t)row * EXTN);
    for (int i = threadIdx.x; i < Vv / 4; i += 256) {
        float4 v = op[i];
        v.x = fmaf(v.x, a, c); v.y = fmaf(v.y, a, c);
        v.z = fmaf(v.z, a, c); v.w = fmaf(v.w, a, c);
        op[i] = v;
    }
    for (int j = Vv + threadIdx.x; j < EXTN; j += 256)
        out[(size_t)row * EXTN + j] = 0.f;
}

// src_map_idx is int32 on the wire (JAX x64-disabled); bounds-guarded.
__global__ void scatter_kernel(float* __restrict__ out,
                               const int* __restrict__ map) {
    int row = blockIdx.x;
    int b = row >> 6;
    float q = 1.f - g_p[row];
    for (int k = threadIdx.x; k < TK; k += blockDim.x) {
        int idx = map[b * TK + k];
        if (idx >= 0 && idx < EXTN)
            atomicAdd(out + (size_t)row * EXTN + (size_t)idx,
                      q * g_att[row * TK + k]);
    }
}

// ---------------- launch ------------------------------------------------------
extern "C" void kernel_launch(void* const* d_in, const int* in_sizes, int n_in,
                              void* d_out, int out_size) {
    const float* tgt    = (const float*)d_in[0];
    const float* src    = (const float*)d_in[1];
    const int*   mp     = (const int*)d_in[2];
    const float* W_out  = (const float*)d_in[3];
    const float* b_out  = (const float*)d_in[4];
    const float* W_attn = (const float*)d_in[5];
    const float* b_attn = (const float*)d_in[6];
    const float* v_w    = (const float*)d_in[7];
    const float* W_lin  = (const float*)d_in[8];
    const float* b_lin  = (const float*)d_in[9];
    float* out = (float*)d_out;

    static int attr_set = 0;
    if (!attr_set) {
        cudaFuncSetAttribute(mma_gemm, cudaFuncAttributeMaxDynamicSharedMemorySize,
                             GEMM_SMEM);
        cudaFuncSetAttribute(qk_gemm, cudaFuncAttributeMaxDynamicSharedMemorySize,
                             GEMM_SMEM);
        attr_set = 1;
    }

    init_kernel<<<2, 256>>>();
    mask_kernel<<<NROW + NKROW, 128>>>(tgt, src);

    // qproj + kproj merged (z=0: qproj 4 M-blocks; z=1: kproj 8 M-blocks)
    qk_gemm<<<dim3(Dd / 128, NKROW / 128, 2), 128, GEMM_SMEM>>>(
        tgt, src, W_attn, b_attn);

    // logits = tgt @ W_out^T + b_out, written straight into out (ldc = EXTN)
    mma_gemm<<<dim3(Vv / 128, NROW / 128), 128, GEMM_SMEM>>>(
        tgt, Dd, W_out, Dd, b_out, out, EXTN, 1);

    attn_kernel<<<NROW, 256>>>(src, v_w, W_lin, b_lin);
    combine_kernel<<<NROW, 256>>>(out);
    scatter_kernel<<<NROW, 128>>>(out, mp);
}

// round 13
// speedup vs baseline: 1.1443x; 1.0658x over previous
#include <cuda_runtime.h>
#include <cuda_bf16.h>
#include <cuda_fp16.h>
#include <cstdint>

// Problem constants
#define Bz   8
#define TQ   64
#define TK   128
#define Dd   512
#define Vv   32000
#define EXTN (Vv + TK)      // 32128
#define NROW (Bz * TQ)      // 512
#define NKROW (Bz * TK)     // 1024

// ---------------- scratch (device globals; ~69.5 MB total, < proven 128MB arena headroom)
__device__ float g_qproj[NROW * Dd];
__device__ float g_kproj[NKROW * Dd];
__device__ float g_att[NROW * TK];
__device__ float g_p[NROW];
__device__ float g_rowsum[NROW];
__device__ float g_rowsq[NROW];
__device__ float g_srcmask[NKROW];
__device__ float g_tgtmask[NROW];
// preconverted fp16 operands for the vocab GEMM
__device__ __align__(16) uint2 g_wout_hi_u2[(size_t)Vv * Dd / 4];  // 32.8 MB
__device__ __align__(16) uint2 g_wout_lo_u2[(size_t)Vv * Dd / 4];  // 32.8 MB
__device__ __align__(16) uint2 g_tgthi_u2[NROW * Dd / 4];          // 0.5 MB

// ---------------- generic helpers -------------------------------------------
__device__ __forceinline__ float warp_sum(float v) {
#pragma unroll
    for (int o = 16; o > 0; o >>= 1) v += __shfl_xor_sync(0xffffffffu, v, o);
    return v;
}
__device__ __forceinline__ float warp_max(float v) {
#pragma unroll
    for (int o = 16; o > 0; o >>= 1) v = fmaxf(v, __shfl_xor_sync(0xffffffffu, v, o));
    return v;
}
__device__ __forceinline__ float block_sum256(float v, float* scr) {
    v = warp_sum(v);
    int w = threadIdx.x >> 5;
    __syncthreads();
    if ((threadIdx.x & 31) == 0) scr[w] = v;
    __syncthreads();
    if (threadIdx.x == 0) {
        float t = 0.f;
#pragma unroll
        for (int i = 0; i < 8; i++) t += scr[i];
        scr[8] = t;
    }
    __syncthreads();
    return scr[8];
}
__device__ __forceinline__ float block_max256(float v, float* scr) {
    v = warp_max(v);
    int w = threadIdx.x >> 5;
    __syncthreads();
    if ((threadIdx.x & 31) == 0) scr[w] = v;
    __syncthreads();
    if (threadIdx.x == 0) {
        float t = scr[0];
#pragma unroll
        for (int i = 1; i < 8; i++) t = fmaxf(t, scr[i]);
        scr[8] = t;
    }
    __syncthreads();
    return scr[8];
}

// FMA-only tanh (proven)
__device__ __forceinline__ float tanh_fast(float x) {
    float z = x * 2.885390081777927f;
    z = fminf(25.f, fmaxf(-25.f, z));
    const float big = 12582912.f;
    float t  = z + big;
    float nf = t - big;
    float f  = z - nf;
    int   n  = __float_as_int(t) - 0x4B400000;
    float p = 1.33335581e-3f;
    p = fmaf(p, f, 9.61804886e-3f);
    p = fmaf(p, f, 5.55041087e-2f);
    p = fmaf(p, f, 2.40226337e-1f);
    p = fmaf(p, f, 6.93147182e-1f);
    p = fmaf(p, f, 1.0f);
    float y = __int_as_float(__float_as_int(p) + (n << 23));
    float d = y + 1.f;
    float r = __int_as_float((int)(0x7EF127EAu - (unsigned)__float_as_int(d)));
    r = r * fmaf(-d, r, 2.f);
    r = r * fmaf(-d, r, 2.f);
    r = r * fmaf(-d, r, 2.f);
    return (y - 1.f) * r;
}
__device__ __forceinline__ uint32_t smem_u32(const void* p) {
    uint32_t a;
    asm("{ .reg .u64 t; cvta.to.shared.u64 t, %1; cvt.u32.u64 %0, t; }"
        : "=r"(a) : "l"(p));
    return a;
}

// value-only fragment types
struct U4 { uint32_t x, y, z, w; };
struct F4 { float x, y, z, w; };

__device__ __forceinline__ U4 ldmx4(uint32_t addr) {
    U4 r;
    asm volatile("ldmatrix.sync.aligned.m8n8.x4.shared.b16 {%0,%1,%2,%3}, [%4];"
                 : "=r"(r.x), "=r"(r.y), "=r"(r.z), "=r"(r.w) : "r"(addr));
    return r;
}
__device__ __forceinline__ void mma(F4& d, const U4& a, uint32_t b0, uint32_t b1) {
    asm volatile("mma.sync.aligned.m16n8k16.row.col.f32.f16.f16.f32 "
        "{%0,%1,%2,%3}, {%4,%5,%6,%7}, {%8,%9}, {%0,%1,%2,%3};"
        : "+f"(d.x), "+f"(d.y), "+f"(d.z), "+f"(d.w)
        : "r"(a.x), "r"(a.y), "r"(a.z), "r"(a.w), "r"(b0), "r"(b1));
}
__device__ __forceinline__ void sts16(uint32_t addr, uint32_t v0, uint32_t v1,
                                      uint32_t v2, uint32_t v3) {
    asm volatile("st.shared.v4.u32 [%0], {%1, %2, %3, %4};"
                 :: "r"(addr), "r"(v0), "r"(v1), "r"(v2), "r"(v3));
}
__device__ __forceinline__ void cp16(uint32_t dst, const void* src) {
    asm volatile("cp.async.cg.shared.global [%0], [%1], 16;" :: "r"(dst), "l"(src));
}

// A: fp32x4 -> packed fp16x2 (hi only)
__device__ __forceinline__ void cvtA4(float4 v, uint2& h) {
    h.x = (uint32_t)__half_as_ushort(__float2half_rn(v.x))
        | ((uint32_t)__half_as_ushort(__float2half_rn(v.y)) << 16);
    h.y = (uint32_t)__half_as_ushort(__float2half_rn(v.z))
        | ((uint32_t)__half_as_ushort(__float2half_rn(v.w)) << 16);
}
// B: scale by 32 (keeps lo out of fp16-denormal range), split hi/lo
#define BSCALE 32.0f
#define BINV   0.03125f
__device__ __forceinline__ void splitB4(float4 v, uint2& h, uint2& l) {
    v.x *= BSCALE; v.y *= BSCALE; v.z *= BSCALE; v.w *= BSCALE;
    __half h0 = __float2half_rn(v.x), h1 = __float2half_rn(v.y);
    __half h2 = __float2half_rn(v.z), h3 = __float2half_rn(v.w);
    __half a0 = __float2half_rn(v.x - __half2float(h0));
    __half a1 = __float2half_rn(v.y - __half2float(h1));
    __half a2 = __float2half_rn(v.z - __half2float(h2));
    __half a3 = __float2half_rn(v.w - __half2float(h3));
    h.x = (uint32_t)__half_as_ushort(h0) | ((uint32_t)__half_as_ushort(h1) << 16);
    h.y = (uint32_t)__half_as_ushort(h2) | ((uint32_t)__half_as_ushort(h3) << 16);
    l.x = (uint32_t)__half_as_ushort(a0) | ((uint32_t)__half_as_ushort(a1) << 16);
    l.y = (uint32_t)__half_as_ushort(a2) | ((uint32_t)__half_as_ushort(a3) << 16);
}

// ---------------- small kernels ----------------------------------------------
__global__ void init_kernel() {
    int i = blockIdx.x * blockDim.x + threadIdx.x;
    if (i < NROW) { g_rowsum[i] = 0.f; g_rowsq[i] = 0.f; }
}

__global__ void mask_kernel(const float* __restrict__ tgt,
                            const float* __restrict__ src) {
    int rb = blockIdx.x;
    const float* p;
    float* dst;
    if (rb < NROW) { p = tgt + (size_t)rb * Dd; dst = &g_tgtmask[rb]; }
    else           { p = src + (size_t)(rb - NROW) * Dd; dst = &g_srcmask[rb - NROW]; }
    float s = 0.f;
    for (int i = threadIdx.x; i < Dd; i += 128) s += fabsf(p[i]);
    s = warp_sum(s);
    __shared__ float sc[4];
    if ((threadIdx.x & 31) == 0) sc[threadIdx.x >> 5] = s;
    __syncthreads();
    if (threadIdx.x == 0)
        *dst = ((sc[0] + sc[1] + sc[2] + sc[3]) > 0.f) ? 1.f : 0.f;
}

// preconvert W_out -> scaled fp16 hi/lo; tgt -> fp16 hi
__global__ void convert_wout(const float4* __restrict__ w, int n4) {
    int i = blockIdx.x * blockDim.x + threadIdx.x;
    if (i >= n4) return;
    uint2 h, l;
    splitB4(w[i], h, l);
    g_wout_hi_u2[i] = h;
    g_wout_lo_u2[i] = l;
}
__global__ void convert_tgt(const float4* __restrict__ x, int n4) {
    int i = blockIdx.x * blockDim.x + threadIdx.x;
    if (i >= n4) return;
    uint2 h;
    cvtA4(x[i], h);
    g_tgthi_u2[i] = h;
}

// ---------------- qk GEMM: fp16 2-product, fp32 in, in-kernel cvt (proven) ---
#define PITCH 80
#define TILE_BYTES (128 * PITCH)
#define T_AHI 0
#define T_BHI TILE_BYTES
#define T_BLO (2 * TILE_BYTES)
#define STAGE_BYTES (3 * TILE_BYTES)
#define GEMM_SMEM (2 * STAGE_BYTES)  // 61440
#define KSTEPS (Dd / 16)             // 32

__device__ __forceinline__ void gemm_core(
    const float* __restrict__ A, int lda,
    const float* __restrict__ B, int ldb,
    const float* __restrict__ bias,
    float* __restrict__ C, int ldc,
    size_t m0, size_t n0, uint8_t* smem_raw) {
    uint32_t smb = smem_u32(smem_raw);

    int tid = threadIdx.x, wid = tid >> 5, lane = tid & 31;
    int warp_m = wid >> 1, warp_n = wid & 1;

    const float* aptr = A + (m0 + (size_t)tid) * (size_t)lda;
    const float* bptr = B + (n0 + (size_t)tid) * (size_t)ldb;
    uint32_t o0 = (uint32_t)(PITCH * tid + 16 * ((tid >> 3) % 5));
    uint32_t o1 = (uint32_t)(PITCH * tid + 16 * (((tid >> 3) + 1) % 5));

    int q = lane >> 3, li = lane & 7;
    uint32_t aof[4], bof[4];
#pragma unroll
    for (int mt = 0; mt < 4; mt++) {
        int r = warp_m * 64 + mt * 16 + (q & 1) * 8 + li;
        aof[mt] = (uint32_t)(PITCH * r + 16 * (((r >> 3) + (q >> 1)) % 5));
    }
#pragma unroll
    for (int c = 0; c < 4; c++) {
        int r = warp_n * 64 + c * 16 + (q >> 1) * 8 + li;
        bof[c] = (uint32_t)(PITCH * r + 16 * (((r >> 3) + (q & 1)) % 5));
    }

    F4 d[4][8];
#pragma unroll
    for (int mt = 0; mt < 4; mt++)
#pragma unroll
        for (int nt = 0; nt < 8; nt++) {
            d[mt][nt].x = 0.f; d[mt][nt].y = 0.f;
            d[mt][nt].z = 0.f; d[mt][nt].w = 0.f;
        }

    float4 pa0 = *(const float4*)(aptr + 0);
    float4 pa1 = *(const float4*)(aptr + 4);
    float4 pa2 = *(const float4*)(aptr + 8);
    float4 pa3 = *(const float4*)(aptr + 12);
    float4 pb0 = *(const float4*)(bptr + 0);
    float4 pb1 = *(const float4*)(bptr + 4);
    float4 pb2 = *(const float4*)(bptr + 8);
    float4 pb3 = *(const float4*)(bptr + 12);

#pragma unroll 1
    for (int s = 0; s < KSTEPS; s++) {
        uint32_t SB = smb + (uint32_t)((s & 1) * STAGE_BYTES);
        {
            uint2 ha0, ha1, ha2, ha3;
            cvtA4(pa0, ha0); cvtA4(pa1, ha1); cvtA4(pa2, ha2); cvtA4(pa3, ha3);
            sts16(SB + T_AHI + o0, ha0.x, ha0.y, ha1.x, ha1.y);
            sts16(SB + T_AHI + o1, ha2.x, ha2.y, ha3.x, ha3.y);
            uint2 h0, l0, h1, l1, h2, l2, h3, l3;
            splitB4(pb0, h0, l0); splitB4(pb1, h1, l1);
            splitB4(pb2, h2, l2); splitB4(pb3, h3, l3);
            sts16(SB + T_BHI + o0, h0.x, h0.y, h1.x, h1.y);
            sts16(SB + T_BHI + o1, h2.x, h2.y, h3.x, h3.y);
            sts16(SB + T_BLO + o0, l0.x, l0.y, l1.x, l1.y);
            sts16(SB + T_BLO + o1, l2.x, l2.y, l3.x, l3.y);
        }
        if (s + 1 < KSTEPS) {
            int k = (s + 1) * 16;
            pa0 = *(const float4*)(aptr + k);
            pa1 = *(const float4*)(aptr + k + 4);
            pa2 = *(const float4*)(aptr + k + 8);
            pa3 = *(const float4*)(aptr + k + 12);
            pb0 = *(const float4*)(bptr + k);
            pb1 = *(const float4*)(bptr + k + 4);
            pb2 = *(const float4*)(bptr + k + 8);
            pb3 = *(const float4*)(bptr + k + 12);
        }
        __syncthreads();

        U4 ah0 = ldmx4(SB + T_AHI + aof[0]);
        U4 ah1 = ldmx4(SB + T_AHI + aof[1]);
        U4 ah2 = ldmx4(SB + T_AHI + aof[2]);
        U4 ah3 = ldmx4(SB + T_AHI + aof[3]);
        U4 bh = ldmx4(SB + T_BHI + bof[0]);
#pragma unroll
        for (int c = 0; c < 4; c++) {
            U4 bl = ldmx4(SB + T_BLO + bof[c]);
            U4 bhn;
            if (c < 3) bhn = ldmx4(SB + T_BHI + bof[c + 1]);
            mma(d[0][2 * c], ah0, bh.x, bh.y); mma(d[0][2 * c + 1], ah0, bh.z, bh.w);
            mma(d[1][2 * c], ah1, bh.x, bh.y); mma(d[1][2 * c + 1], ah1, bh.z, bh.w);
            mma(d[2][2 * c], ah2, bh.x, bh.y); mma(d[2][2 * c + 1], ah2, bh.z, bh.w);
            mma(d[3][2 * c], ah3, bh.x, bh.y); mma(d[3][2 * c + 1], ah3, bh.z, bh.w);
            mma(d[0][2 * c], ah0, bl.x, bl.y); mma(d[0][2 * c + 1], ah0, bl.z, bl.w);
            mma(d[1][2 * c], ah1, bl.x, bl.y); mma(d[1][2 * c + 1], ah1, bl.z, bl.w);
            mma(d[2][2 * c], ah2, bl.x, bl.y); mma(d[2][2 * c + 1], ah2, bl.z, bl.w);
            mma(d[3][2 * c], ah3, bl.x, bl.y); mma(d[3][2 * c + 1], ah3, bl.z, bl.w);
            bh = bhn;
        }
        __syncthreads();
    }

    int groupl = lane >> 2, subl = lane & 3;
    int colbase = (int)n0 + warp_n * 64 + subl * 2;
#pragma unroll
    for (int mt = 0; mt < 4; mt++) {
#pragma unroll
        for (int half = 0; half < 2; half++) {
            size_t r = m0 + (size_t)(warp_m * 64 + mt * 16 + half * 8 + groupl);
            float* crow = C + r * (size_t)ldc + colbase;
#pragma unroll
            for (int nt = 0; nt < 8; nt++) {
                float v0 = (half ? d[mt][nt].z : d[mt][nt].x) * BINV;
                float v1 = (half ? d[mt][nt].w : d[mt][nt].y) * BINV;
                if (bias) {
                    v0 += __ldg(bias + colbase + nt * 8);
                    v1 += __ldg(bias + colbase + nt * 8 + 1);
                }
                *(float2*)(crow + nt * 8) = make_float2(v0, v1);
            }
        }
    }
}

// merged qproj + kproj
__global__ __launch_bounds__(128, 2)
void qk_gemm(const float* __restrict__ tgt, const float* __restrict__ src,
             const float* __restrict__ W_attn, const float* __restrict__ b_attn) {
    extern __shared__ __align__(16) uint8_t smbuf[];
    if (blockIdx.z == 0) {
        if (blockIdx.y >= NROW / 128) return;
        gemm_core(tgt, Dd, W_attn, 2 * Dd, b_attn, g_qproj, Dd,
                  (size_t)blockIdx.y * 128, (size_t)blockIdx.x * 128, smbuf);
    } else {
        gemm_core(src, Dd, W_attn + Dd, 2 * Dd, nullptr, g_kproj, Dd,
                  (size_t)blockIdx.y * 128, (size_t)blockIdx.x * 128, smbuf);
    }
}

// ---------------- logits GEMM: preconverted fp16 + cp.async, 3-stage ---------
// tiles fp16, 128 rows, pitch 48, slot rotation mod 3 (conflict-free verified)
#define LPITCH 48
#define LTILE (128 * LPITCH)          // 6144
#define LT_A  0
#define LT_BH LTILE
#define LT_BL (2 * LTILE)
#define LSTAGE (3 * LTILE)            // 18432
#define LSMEM (3 * LSTAGE)            // 55296

__device__ __forceinline__ void l_issue(uint32_t SB, int s,
    const __half* a, const __half* bh, const __half* bl,
    uint32_t o0, uint32_t o1) {
    const char* ap  = (const char*)(a + s * 16);
    const char* bhp = (const char*)(bh + s * 16);
    const char* blp = (const char*)(bl + s * 16);
    cp16(SB + LT_A + o0, ap);
    cp16(SB + LT_A + o1, ap + 16);
    cp16(SB + LT_BH + o0, bhp);
    cp16(SB + LT_BH + o1, bhp + 16);
    cp16(SB + LT_BL + o0, blp);
    cp16(SB + LT_BL + o1, blp + 16);
    asm volatile("cp.async.commit_group;" ::: "memory");
}

__global__ __launch_bounds__(128, 2)
void logits_gemm(const float* __restrict__ bias, float* __restrict__ C) {
    extern __shared__ __align__(16) uint8_t smbuf[];
    uint32_t smb = smem_u32(smbuf);

    int tid = threadIdx.x, wid = tid >> 5, lane = tid & 31;
    int warp_m = wid >> 1, warp_n = wid & 1;
    size_t m0 = (size_t)blockIdx.y * 128;
    size_t n0 = (size_t)blockIdx.x * 128;

    const __half* aptr = (const __half*)g_tgthi_u2 + (m0 + (size_t)tid) * Dd;
    const __half* bhp  = (const __half*)g_wout_hi_u2 + (n0 + (size_t)tid) * Dd;
    const __half* blp  = (const __half*)g_wout_lo_u2 + (n0 + (size_t)tid) * Dd;
    uint32_t o0 = (uint32_t)(LPITCH * tid + 16 * ((tid >> 3) % 3));
    uint32_t o1 = (uint32_t)(LPITCH * tid + 16 * (((tid >> 3) + 1) % 3));

    int q = lane >> 3, li = lane & 7;
    uint32_t aof[4], bof[4];
#pragma unroll
    for (int mt = 0; mt < 4; mt++) {
        int r = warp_m * 64 + mt * 16 + (q & 1) * 8 + li;
        aof[mt] = (uint32_t)(LPITCH * r + 16 * (((r >> 3) + (q >> 1)) % 3));
    }
#pragma unroll
    for (int c = 0; c < 4; c++) {
        int r = warp_n * 64 + c * 16 + (q >> 1) * 8 + li;
        bof[c] = (uint32_t)(LPITCH * r + 16 * (((r >> 3) + (q & 1)) % 3));
    }

    F4 d[4][8];
#pragma unroll
    for (int mt = 0; mt < 4; mt++)
#pragma unroll
        for (int nt = 0; nt < 8; nt++) {
            d[mt][nt].x = 0.f; d[mt][nt].y = 0.f;
            d[mt][nt].z = 0.f; d[mt][nt].w = 0.f;
        }

    // prologue: stages 0 and 1
    l_issue(smb + 0 * LSTAGE, 0, aptr, bhp, blp, o0, o1);
    l_issue(smb + 1 * LSTAGE, 1, aptr, bhp, blp, o0, o1);

#pragma unroll 1
    for (int s = 0; s < KSTEPS; s++) {
        if (s + 1 < KSTEPS)
            asm volatile("cp.async.wait_group 1;" ::: "memory");
        else
            asm volatile("cp.async.wait_group 0;" ::: "memory");
        __syncthreads();
        if (s + 2 < KSTEPS)
            l_issue(smb + (uint32_t)(((s + 2) % 3) * LSTAGE), s + 2,
                    aptr, bhp, blp, o0, o1);

        uint32_t SB = smb + (uint32_t)((s % 3) * LSTAGE);
        U4 ah0 = ldmx4(SB + LT_A + aof[0]);
        U4 ah1 = ldmx4(SB + LT_A + aof[1]);
        U4 ah2 = ldmx4(SB + LT_A + aof[2]);
        U4 ah3 = ldmx4(SB + LT_A + aof[3]);
        U4 bh = ldmx4(SB + LT_BH + bof[0]);
#pragma unroll
        for (int c = 0; c < 4; c++) {
            U4 bl = ldmx4(SB + LT_BL + bof[c]);
            U4 bhn;
            if (c < 3) bhn = ldmx4(SB + LT_BH + bof[c + 1]);
            mma(d[0][2 * c], ah0, bh.x, bh.y); mma(d[0][2 * c + 1], ah0, bh.z, bh.w);
            mma(d[1][2 * c], ah1, bh.x, bh.y); mma(d[1][2 * c + 1], ah1, bh.z, bh.w);
            mma(d[2][2 * c], ah2, bh.x, bh.y); mma(d[2][2 * c + 1], ah2, bh.z, bh.w);
            mma(d[3][2 * c], ah3, bh.x, bh.y); mma(d[3][2 * c + 1], ah3, bh.z, bh.w);
            mma(d[0][2 * c], ah0, bl.x, bl.y); mma(d[0][2 * c + 1], ah0, bl.z, bl.w);
            mma(d[1][2 * c], ah1, bl.x, bl.y); mma(d[1][2 * c + 1], ah1, bl.z, bl.w);
            mma(d[2][2 * c], ah2, bl.x, bl.y); mma(d[2][2 * c + 1], ah2, bl.z, bl.w);
            mma(d[3][2 * c], ah3, bl.x, bl.y); mma(d[3][2 * c + 1], ah3, bl.z, bl.w);
            bh = bhn;
        }
    }

    // epilogue with bias + per-row stats for the vocab layernorm
    int groupl = lane >> 2, subl = lane & 3;
    int colbase = (int)n0 + warp_n * 64 + subl * 2;
#pragma unroll
    for (int mt = 0; mt < 4; mt++) {
#pragma unroll
        for (int half = 0; half < 2; half++) {
            size_t r = m0 + (size_t)(warp_m * 64 + mt * 16 + half * 8 + groupl);
            float* crow = C + r * (size_t)EXTN + colbase;
            float ssum = 0.f, sq = 0.f;
#pragma unroll
            for (int nt = 0; nt < 8; nt++) {
                float v0 = (half ? d[mt][nt].z : d[mt][nt].x) * BINV;
                float v1 = (half ? d[mt][nt].w : d[mt][nt].y) * BINV;
                v0 += __ldg(bias + colbase + nt * 8);
                v1 += __ldg(bias + colbase + nt * 8 + 1);
                *(float2*)(crow + nt * 8) = make_float2(v0, v1);
                ssum += v0 + v1;
                sq += fmaf(v0, v0, v1 * v1);
            }
            ssum += __shfl_xor_sync(0xffffffffu, ssum, 1);
            ssum += __shfl_xor_sync(0xffffffffu, ssum, 2);
            sq   += __shfl_xor_sync(0xffffffffu, sq, 1);
            sq   += __shfl_xor_sync(0xffffffffu, sq, 2);
            if (subl == 0) {
                atomicAdd(&g_rowsum[r], ssum);
                atomicAdd(&g_rowsq[r], sq);
            }
        }
    }
}

// ---------------- fused additive attention -----------------------------------
__global__ __launch_bounds__(256)
void attn_kernel(const float* __restrict__ src, const float* __restrict__ v_w,
                 const float* __restrict__ W_lin, const float* __restrict__ b_lin) {
    __shared__ float qp[Dd];
    __shared__ float vw[Dd];
    __shared__ float sraw[TK];
    __shared__ float sprob[TK];
    __shared__ float scr[9];

    int row = blockIdx.x;
    int b = row >> 6;
    int tid = threadIdx.x, lane = tid & 31, w = tid >> 5;

    for (int i = tid; i < Dd; i += 256) {
        qp[i] = g_qproj[row * Dd + i];
        vw[i] = v_w[i];
    }
    float tm = g_tgtmask[row];
    __syncthreads();

    float qpr[16], vwr[16];
#pragma unroll
    for (int j = 0; j < 16; j++) {
        qpr[j] = qp[lane + 32 * j];
        vwr[j] = vw[lane + 32 * j];
    }

    for (int k = w; k < TK; k += 8) {
        const float* kp = g_kproj + ((size_t)(b * TK + k)) * Dd;
        float acc = 0.f;
#pragma unroll
        for (int j = 0; j < 16; j++)
            acc += tanh_fast(qpr[j] + __ldg(kp + lane + 32 * j)) * vwr[j];
        acc = warp_sum(acc);
        if (lane == 0) sraw[k] = acc;
    }
    __syncthreads();

    float raw = 0.f, smk = 0.f;
    if (tid < TK) { raw = sraw[tid]; smk = g_srcmask[b * TK + tid]; }
    float masked = (tid < TK) ? ((smk == 0.f) ? -1e30f : raw) : -1e30f;
    float mx = block_max256(masked, scr);
    float e = (tid < TK) ? __expf(masked - mx) : 0.f;
    float ssum = block_sum256(e, scr);
    if (tid < TK) sprob[tid] = e / ssum;

    float oa = (tid < TK) ? raw * smk * tm : 0.f;
    float osum = block_sum256(oa, scr);
    float osq  = block_sum256(oa * oa, scr);

    float zacc = 0.f;
    for (int dd = tid; dd < Dd; dd += 256) {
        float wv = 0.f;
        const float* sp = src + ((size_t)b * TK) * Dd + dd;
#pragma unroll 4
        for (int k = 0; k < TK; k++) wv = fmaf(sprob[k], sp[(size_t)k * Dd], wv);
        wv *= tm;
        zacc = fmaf(wv, W_lin[dd], zacc);
    }
    float z = block_sum256(zacc, scr);
    if (tid == 0) g_p[row] = 1.f / (1.f + __expf(-(z + b_lin[0])));

    float mean = osum * (1.f / (float)TK);
    float var = osq * (1.f / (float)TK) - mean * mean;
    float inv = rsqrtf(var + 1e-5f);
    if (tid < TK) g_att[row * TK + tid] = (oa - mean) * inv;
}

// ---------------- combine (in-place on out) + scatter -------------------------
__global__ __launch_bounds__(256)
void combine_kernel(float* __restrict__ out) {
    int row = blockIdx.x;
    float mean = g_rowsum[row] * (1.f / (float)Vv);
    float var = g_rowsq[row] * (1.f / (float)Vv) - mean * mean;
    float inv = rsqrtf(var + 1e-5f);
    float pv = g_p[row];
    float a = inv * pv;
    float c = -mean * inv * pv;
    float4* op = (float4*)(out + (size_t)row * EXTN);
    for (int i = threadIdx.x; i < Vv / 4; i += 256) {
        float4 v = op[i];
        v.x = fmaf(v.x, a, c); v.y = fmaf(v.y, a, c);
        v.z = fmaf(v.z, a, c); v.w = fmaf(v.w, a, c);
        op[i] = v;
    }
    for (int j = Vv + threadIdx.x; j < EXTN; j += 256)
        out[(size_t)row * EXTN + j] = 0.f;
}

// src_map_idx is int32 on the wire (JAX x64-disabled); bounds-guarded.
__global__ void scatter_kernel(float* __restrict__ out,
                               const int* __restrict__ map) {
    int row = blockIdx.x;
    int b = row >> 6;
    float q = 1.f - g_p[row];
    for (int k = threadIdx.x; k < TK; k += blockDim.x) {
        int idx = map[b * TK + k];
        if (idx >= 0 && idx < EXTN)
            atomicAdd(out + (size_t)row * EXTN + (size_t)idx,
                      q * g_att[row * TK + k]);
    }
}

// ---------------- launch ------------------------------------------------------
extern "C" void kernel_launch(void* const* d_in, const int* in_sizes, int n_in,
                              void* d_out, int out_size) {
    const float* tgt    = (const float*)d_in[0];
    const float* src    = (const float*)d_in[1];
    const int*   mp     = (const int*)d_in[2];
    const float* W_out  = (const float*)d_in[3];
    const float* b_out  = (const float*)d_in[4];
    const float* W_attn = (const float*)d_in[5];
    const float* b_attn = (const float*)d_in[6];
    const float* v_w    = (const float*)d_in[7];
    const float* W_lin  = (const float*)d_in[8];
    const float* b_lin  = (const float*)d_in[9];
    float* out = (float*)d_out;

    static int attr_set = 0;
    if (!attr_set) {
        cudaFuncSetAttribute(qk_gemm, cudaFuncAttributeMaxDynamicSharedMemorySize,
                             GEMM_SMEM);
        cudaFuncSetAttribute(logits_gemm, cudaFuncAttributeMaxDynamicSharedMemorySize,
                             LSMEM);
        attr_set = 1;
    }

    init_kernel<<<2, 256>>>();
    mask_kernel<<<NROW + NKROW, 128>>>(tgt, src);

    // preconvert operands for the vocab GEMM
    {
        int n4 = (int)((size_t)Vv * Dd / 4);
        convert_wout<<<(n4 + 255) / 256, 256>>>((const float4*)W_out, n4);
        n4 = NROW * Dd / 4;
        convert_tgt<<<(n4 + 255) / 256, 256>>>((const float4*)tgt, n4);
    }

    // qproj + kproj merged (z=0: qproj 4 M-blocks; z=1: kproj 8 M-blocks)
    qk_gemm<<<dim3(Dd / 128, NKROW / 128, 2), 128, GEMM_SMEM>>>(
        tgt, src, W_attn, b_attn);

    // logits = tgt @ W_out^T + b_out, written straight into out (ldc = EXTN)
    logits_gemm<<<dim3(Vv / 128, NROW / 128), 128, LSMEM>>>(b_out, out);

    attn_kernel<<<NROW, 256>>>(src, v_w, W_lin, b_lin);
    combine_kernel<<<NROW, 256>>>(out);
    scatter_kernel<<<NROW, 128>>>(out, mp);
}

// round 16
// speedup vs baseline: 1.4412x; 1.2595x over previous
#include <cuda_runtime.h>
#include <cuda_bf16.h>
#include <cuda_fp16.h>
#include <cstdint>

// Problem constants
#define Bz   8
#define TQ   64
#define TK   128
#define Dd   512
#define Vv   32000
#define EXTN (Vv + TK)      // 32128
#define NROW (Bz * TQ)      // 512
#define NKROW (Bz * TK)     // 1024

// ---------------- scratch (device globals; ~37 MB total) ---------------------
__device__ float g_qproj[NROW * Dd];
__device__ float g_kproj[NKROW * Dd];
__device__ float g_att[NROW * TK];
__device__ float g_p[NROW];
__device__ float g_rowsum[NROW];
__device__ float g_rowsq[NROW];
__device__ float g_srcmask[NKROW];
__device__ float g_tgtmask[NROW];
// preconverted fp16 operands for the vocab GEMM (single-product scheme)
__device__ __align__(16) uint2 g_wout_hi_u2[(size_t)Vv * Dd / 4];  // 32.8 MB
__device__ __align__(16) uint2 g_tgthi_u2[NROW * Dd / 4];          // 0.5 MB

// ---------------- generic helpers -------------------------------------------
__device__ __forceinline__ float warp_sum(float v) {
#pragma unroll
    for (int o = 16; o > 0; o >>= 1) v += __shfl_xor_sync(0xffffffffu, v, o);
    return v;
}
__device__ __forceinline__ float warp_max(float v) {
#pragma unroll
    for (int o = 16; o > 0; o >>= 1) v = fmaxf(v, __shfl_xor_sync(0xffffffffu, v, o));
    return v;
}
__device__ __forceinline__ float block_sum256(float v, float* scr) {
    v = warp_sum(v);
    int w = threadIdx.x >> 5;
    __syncthreads();
    if ((threadIdx.x & 31) == 0) scr[w] = v;
    __syncthreads();
    if (threadIdx.x == 0) {
        float t = 0.f;
#pragma unroll
        for (int i = 0; i < 8; i++) t += scr[i];
        scr[8] = t;
    }
    __syncthreads();
    return scr[8];
}
__device__ __forceinline__ float block_max256(float v, float* scr) {
    v = warp_max(v);
    int w = threadIdx.x >> 5;
    __syncthreads();
    if ((threadIdx.x & 31) == 0) scr[w] = v;
    __syncthreads();
    if (threadIdx.x == 0) {
        float t = scr[0];
#pragma unroll
        for (int i = 1; i < 8; i++) t = fmaxf(t, scr[i]);
        scr[8] = t;
    }
    __syncthreads();
    return scr[8];
}

// FMA-only tanh (proven)
__device__ __forceinline__ float tanh_fast(float x) {
    float z = x * 2.885390081777927f;
    z = fminf(25.f, fmaxf(-25.f, z));
    const float big = 12582912.f;
    float t  = z + big;
    float nf = t - big;
    float f  = z - nf;
    int   n  = __float_as_int(t) - 0x4B400000;
    float p = 1.33335581e-3f;
    p = fmaf(p, f, 9.61804886e-3f);
    p = fmaf(p, f, 5.55041087e-2f);
    p = fmaf(p, f, 2.40226337e-1f);
    p = fmaf(p, f, 6.93147182e-1f);
    p = fmaf(p, f, 1.0f);
    float y = __int_as_float(__float_as_int(p) + (n << 23));
    float d = y + 1.f;
    float r = __int_as_float((int)(0x7EF127EAu - (unsigned)__float_as_int(d)));
    r = r * fmaf(-d, r, 2.f);
    r = r * fmaf(-d, r, 2.f);
    r = r * fmaf(-d, r, 2.f);
    return (y - 1.f) * r;
}
__device__ __forceinline__ uint32_t smem_u32(const void* p) {
    uint32_t a;
    asm("{ .reg .u64 t; cvta.to.shared.u64 t, %1; cvt.u32.u64 %0, t; }"
        : "=r"(a) : "l"(p));
    return a;
}

// value-only fragment types
struct U4 { uint32_t x, y, z, w; };
struct F4 { float x, y, z, w; };

__device__ __forceinline__ U4 ldmx4(uint32_t addr) {
    U4 r;
    asm volatile("ldmatrix.sync.aligned.m8n8.x4.shared.b16 {%0,%1,%2,%3}, [%4];"
                 : "=r"(r.x), "=r"(r.y), "=r"(r.z), "=r"(r.w) : "r"(addr));
    return r;
}
__device__ __forceinline__ void mma(F4& d, const U4& a, uint32_t b0, uint32_t b1) {
    asm volatile("mma.sync.aligned.m16n8k16.row.col.f32.f16.f16.f32 "
        "{%0,%1,%2,%3}, {%4,%5,%6,%7}, {%8,%9}, {%0,%1,%2,%3};"
        : "+f"(d.x), "+f"(d.y), "+f"(d.z), "+f"(d.w)
        : "r"(a.x), "r"(a.y), "r"(a.z), "r"(a.w), "r"(b0), "r"(b1));
}
__device__ __forceinline__ void sts16(uint32_t addr, uint32_t v0, uint32_t v1,
                                      uint32_t v2, uint32_t v3) {
    asm volatile("st.shared.v4.u32 [%0], {%1, %2, %3, %4};"
                 :: "r"(addr), "r"(v0), "r"(v1), "r"(v2), "r"(v3));
}
__device__ __forceinline__ void cp16(uint32_t dst, const void* src) {
    asm volatile("cp.async.cg.shared.global [%0], [%1], 16;" :: "r"(dst), "l"(src));
}

// A: fp32x4 -> packed fp16x2 (hi only)
__device__ __forceinline__ void cvtA4(float4 v, uint2& h) {
    h.x = (uint32_t)__half_as_ushort(__float2half_rn(v.x))
        | ((uint32_t)__half_as_ushort(__float2half_rn(v.y)) << 16);
    h.y = (uint32_t)__half_as_ushort(__float2half_rn(v.z))
        | ((uint32_t)__half_as_ushort(__float2half_rn(v.w)) << 16);
}
// B: scale by 32 (keeps values out of fp16-denormal range), split hi/lo
#define BSCALE 32.0f
#define BINV   0.03125f
__device__ __forceinline__ void splitB4(float4 v, uint2& h, uint2& l) {
    v.x *= BSCALE; v.y *= BSCALE; v.z *= BSCALE; v.w *= BSCALE;
    __half h0 = __float2half_rn(v.x), h1 = __float2half_rn(v.y);
    __half h2 = __float2half_rn(v.z), h3 = __float2half_rn(v.w);
    __half a0 = __float2half_rn(v.x - __half2float(h0));
    __half a1 = __float2half_rn(v.y - __half2float(h1));
    __half a2 = __float2half_rn(v.z - __half2float(h2));
    __half a3 = __float2half_rn(v.w - __half2float(h3));
    h.x = (uint32_t)__half_as_ushort(h0) | ((uint32_t)__half_as_ushort(h1) << 16);
    h.y = (uint32_t)__half_as_ushort(h2) | ((uint32_t)__half_as_ushort(h3) << 16);
    l.x = (uint32_t)__half_as_ushort(a0) | ((uint32_t)__half_as_ushort(a1) << 16);
    l.y = (uint32_t)__half_as_ushort(a2) | ((uint32_t)__half_as_ushort(a3) << 16);
}

// ---------------- small kernels ----------------------------------------------
__global__ void init_kernel() {
    int i = blockIdx.x * blockDim.x + threadIdx.x;
    if (i < NROW) { g_rowsum[i] = 0.f; g_rowsq[i] = 0.f; }
}

__global__ void mask_kernel(const float* __restrict__ tgt,
                            const float* __restrict__ src) {
    int rb = blockIdx.x;
    const float* p;
    float* dst;
    if (rb < NROW) { p = tgt + (size_t)rb * Dd; dst = &g_tgtmask[rb]; }
    else           { p = src + (size_t)(rb - NROW) * Dd; dst = &g_srcmask[rb - NROW]; }
    float s = 0.f;
    for (int i = threadIdx.x; i < Dd; i += 128) s += fabsf(p[i]);
    s = warp_sum(s);
    __shared__ float sc[4];
    if ((threadIdx.x & 31) == 0) sc[threadIdx.x >> 5] = s;
    __syncthreads();
    if (threadIdx.x == 0)
        *dst = ((sc[0] + sc[1] + sc[2] + sc[3]) > 0.f) ? 1.f : 0.f;
}

// preconvert W_out -> scaled fp16 hi; tgt -> fp16 hi
__global__ void convert_wout(const float4* __restrict__ w, int n4) {
    int i = blockIdx.x * blockDim.x + threadIdx.x;
    if (i >= n4) return;
    float4 v = w[i];
    v.x *= BSCALE; v.y *= BSCALE; v.z *= BSCALE; v.w *= BSCALE;
    uint2 h;
    cvtA4(v, h);
    g_wout_hi_u2[i] = h;
}
__global__ void convert_tgt(const float4* __restrict__ x, int n4) {
    int i = blockIdx.x * blockDim.x + threadIdx.x;
    if (i >= n4) return;
    uint2 h;
    cvtA4(x[i], h);
    g_tgthi_u2[i] = h;
}

// ---------------- qk GEMM: fp16 2-product, fp32 in, in-kernel cvt (proven) ---
#define PITCH 80
#define TILE_BYTES (128 * PITCH)
#define T_AHI 0
#define T_BHI TILE_BYTES
#define T_BLO (2 * TILE_BYTES)
#define STAGE_BYTES (3 * TILE_BYTES)
#define GEMM_SMEM (2 * STAGE_BYTES)  // 61440
#define KSTEPS (Dd / 16)             // 32

__device__ __forceinline__ void gemm_core(
    const float* __restrict__ A, int lda,
    const float* __restrict__ B, int ldb,
    const float* __restrict__ bias,
    float* __restrict__ C, int ldc,
    size_t m0, size_t n0, uint8_t* smem_raw) {
    uint32_t smb = smem_u32(smem_raw);

    int tid = threadIdx.x, wid = tid >> 5, lane = tid & 31;
    int warp_m = wid >> 1, warp_n = wid & 1;

    const float* aptr = A + (m0 + (size_t)tid) * (size_t)lda;
    const float* bptr = B + (n0 + (size_t)tid) * (size_t)ldb;
    uint32_t o0 = (uint32_t)(PITCH * tid + 16 * ((tid >> 3) % 5));
    uint32_t o1 = (uint32_t)(PITCH * tid + 16 * (((tid >> 3) + 1) % 5));

    int q = lane >> 3, li = lane & 7;
    uint32_t aof[4], bof[4];
#pragma unroll
    for (int mt = 0; mt < 4; mt++) {
        int r = warp_m * 64 + mt * 16 + (q & 1) * 8 + li;
        aof[mt] = (uint32_t)(PITCH * r + 16 * (((r >> 3) + (q >> 1)) % 5));
    }
#pragma unroll
    for (int c = 0; c < 4; c++) {
        int r = warp_n * 64 + c * 16 + (q >> 1) * 8 + li;
        bof[c] = (uint32_t)(PITCH * r + 16 * (((r >> 3) + (q & 1)) % 5));
    }

    F4 d[4][8];
#pragma unroll
    for (int mt = 0; mt < 4; mt++)
#pragma unroll
        for (int nt = 0; nt < 8; nt++) {
            d[mt][nt].x = 0.f; d[mt][nt].y = 0.f;
            d[mt][nt].z = 0.f; d[mt][nt].w = 0.f;
        }

    float4 pa0 = *(const float4*)(aptr + 0);
    float4 pa1 = *(const float4*)(aptr + 4);
    float4 pa2 = *(const float4*)(aptr + 8);
    float4 pa3 = *(const float4*)(aptr + 12);
    float4 pb0 = *(const float4*)(bptr + 0);
    float4 pb1 = *(const float4*)(bptr + 4);
    float4 pb2 = *(const float4*)(bptr + 8);
    float4 pb3 = *(const float4*)(bptr + 12);

#pragma unroll 1
    for (int s = 0; s < KSTEPS; s++) {
        uint32_t SB = smb + (uint32_t)((s & 1) * STAGE_BYTES);
        {
            uint2 ha0, ha1, ha2, ha3;
            cvtA4(pa0, ha0); cvtA4(pa1, ha1); cvtA4(pa2, ha2); cvtA4(pa3, ha3);
            sts16(SB + T_AHI + o0, ha0.x, ha0.y, ha1.x, ha1.y);
            sts16(SB + T_AHI + o1, ha2.x, ha2.y, ha3.x, ha3.y);
            uint2 h0, l0, h1, l1, h2, l2, h3, l3;
            splitB4(pb0, h0, l0); splitB4(pb1, h1, l1);
            splitB4(pb2, h2, l2); splitB4(pb3, h3, l3);
            sts16(SB + T_BHI + o0, h0.x, h0.y, h1.x, h1.y);
            sts16(SB + T_BHI + o1, h2.x, h2.y, h3.x, h3.y);
            sts16(SB + T_BLO + o0, l0.x, l0.y, l1.x, l1.y);
            sts16(SB + T_BLO + o1, l2.x, l2.y, l3.x, l3.y);
        }
        if (s + 1 < KSTEPS) {
            int k = (s + 1) * 16;
            pa0 = *(const float4*)(aptr + k);
            pa1 = *(const float4*)(aptr + k + 4);
            pa2 = *(const float4*)(aptr + k + 8);
            pa3 = *(const float4*)(aptr + k + 12);
            pb0 = *(const float4*)(bptr + k);
            pb1 = *(const float4*)(bptr + k + 4);
            pb2 = *(const float4*)(bptr + k + 8);
            pb3 = *(const float4*)(bptr + k + 12);
        }
        __syncthreads();

        U4 ah0 = ldmx4(SB + T_AHI + aof[0]);
        U4 ah1 = ldmx4(SB + T_AHI + aof[1]);
        U4 ah2 = ldmx4(SB + T_AHI + aof[2]);
        U4 ah3 = ldmx4(SB + T_AHI + aof[3]);
        U4 bh = ldmx4(SB + T_BHI + bof[0]);
#pragma unroll
        for (int c = 0; c < 4; c++) {
            U4 bl = ldmx4(SB + T_BLO + bof[c]);
            U4 bhn;
            if (c < 3) bhn = ldmx4(SB + T_BHI + bof[c + 1]);
            mma(d[0][2 * c], ah0, bh.x, bh.y); mma(d[0][2 * c + 1], ah0, bh.z, bh.w);
            mma(d[1][2 * c], ah1, bh.x, bh.y); mma(d[1][2 * c + 1], ah1, bh.z, bh.w);
            mma(d[2][2 * c], ah2, bh.x, bh.y); mma(d[2][2 * c + 1], ah2, bh.z, bh.w);
            mma(d[3][2 * c], ah3, bh.x, bh.y); mma(d[3][2 * c + 1], ah3, bh.z, bh.w);
            mma(d[0][2 * c], ah0, bl.x, bl.y); mma(d[0][2 * c + 1], ah0, bl.z, bl.w);
            mma(d[1][2 * c], ah1, bl.x, bl.y); mma(d[1][2 * c + 1], ah1, bl.z, bl.w);
            mma(d[2][2 * c], ah2, bl.x, bl.y); mma(d[2][2 * c + 1], ah2, bl.z, bl.w);
            mma(d[3][2 * c], ah3, bl.x, bl.y); mma(d[3][2 * c + 1], ah3, bl.z, bl.w);
            bh = bhn;
        }
        __syncthreads();
    }

    int groupl = lane >> 2, subl = lane & 3;
    int colbase = (int)n0 + warp_n * 64 + subl * 2;
#pragma unroll
    for (int mt = 0; mt < 4; mt++) {
#pragma unroll
        for (int half = 0; half < 2; half++) {
            size_t r = m0 + (size_t)(warp_m * 64 + mt * 16 + half * 8 + groupl);
            float* crow = C + r * (size_t)ldc + colbase;
#pragma unroll
            for (int nt = 0; nt < 8; nt++) {
                float v0 = (half ? d[mt][nt].z : d[mt][nt].x) * BINV;
                float v1 = (half ? d[mt][nt].w : d[mt][nt].y) * BINV;
                if (bias) {
                    v0 += __ldg(bias + colbase + nt * 8);
                    v1 += __ldg(bias + colbase + nt * 8 + 1);
                }
                *(float2*)(crow + nt * 8) = make_float2(v0, v1);
            }
        }
    }
}

// merged qproj + kproj
__global__ __launch_bounds__(128, 2)
void qk_gemm(const float* __restrict__ tgt, const float* __restrict__ src,
             const float* __restrict__ W_attn, const float* __restrict__ b_attn) {
    extern __shared__ __align__(16) uint8_t smbuf[];
    if (blockIdx.z == 0) {
        if (blockIdx.y >= NROW / 128) return;
        gemm_core(tgt, Dd, W_attn, 2 * Dd, b_attn, g_qproj, Dd,
                  (size_t)blockIdx.y * 128, (size_t)blockIdx.x * 128, smbuf);
    } else {
        gemm_core(src, Dd, W_attn + Dd, 2 * Dd, nullptr, g_kproj, Dd,
                  (size_t)blockIdx.y * 128, (size_t)blockIdx.x * 128, smbuf);
    }
}

// ---------------- logits GEMM: single-product fp16, cp.async, 3-stage --------
// tiles fp16, 128 rows, pitch 48, slot rotation mod 3 (conflict-free, proven)
#define LPITCH 48
#define LTILE (128 * LPITCH)          // 6144
#define LT_A  0
#define LT_BH LTILE
#define LSTAGE (2 * LTILE)            // 12288
#define LSMEM (3 * LSTAGE)            // 36864

__device__ __forceinline__ void l_issue(uint32_t SB, int s,
    const __half* a, const __half* bh, uint32_t o0, uint32_t o1) {
    const char* ap  = (const char*)(a + s * 16);
    const char* bhp = (const char*)(bh + s * 16);
    cp16(SB + LT_A + o0, ap);
    cp16(SB + LT_A + o1, ap + 16);
    cp16(SB + LT_BH + o0, bhp);
    cp16(SB + LT_BH + o1, bhp + 16);
    asm volatile("cp.async.commit_group;" ::: "memory");
}

__global__ __launch_bounds__(128, 2)
void logits_gemm(const float* __restrict__ bias, float* __restrict__ C) {
    extern __shared__ __align__(16) uint8_t smbuf[];
    uint32_t smb = smem_u32(smbuf);

    int tid = threadIdx.x, wid = tid >> 5, lane = tid & 31;
    int warp_m = wid >> 1, warp_n = wid & 1;
    size_t m0 = (size_t)blockIdx.y * 128;
    size_t n0 = (size_t)blockIdx.x * 128;

    const __half* aptr = (const __half*)g_tgthi_u2 + (m0 + (size_t)tid) * Dd;
    const __half* bhp  = (const __half*)g_wout_hi_u2 + (n0 + (size_t)tid) * Dd;
    uint32_t o0 = (uint32_t)(LPITCH * tid + 16 * ((tid >> 3) % 3));
    uint32_t o1 = (uint32_t)(LPITCH * tid + 16 * (((tid >> 3) + 1) % 3));

    int q = lane >> 3, li = lane & 7;
    uint32_t aof[4], bof[4];
#pragma unroll
    for (int mt = 0; mt < 4; mt++) {
        int r = warp_m * 64 + mt * 16 + (q & 1) * 8 + li;
        aof[mt] = (uint32_t)(LPITCH * r + 16 * (((r >> 3) + (q >> 1)) % 3));
    }
#pragma unroll
    for (int c = 0; c < 4; c++) {
        int r = warp_n * 64 + c * 16 + (q >> 1) * 8 + li;
        bof[c] = (uint32_t)(LPITCH * r + 16 * (((r >> 3) + (q & 1)) % 3));
    }

    F4 d[4][8];
#pragma unroll
    for (int mt = 0; mt < 4; mt++)
#pragma unroll
        for (int nt = 0; nt < 8; nt++) {
            d[mt][nt].x = 0.f; d[mt][nt].y = 0.f;
            d[mt][nt].z = 0.f; d[mt][nt].w = 0.f;
        }

    l_issue(smb + 0 * LSTAGE, 0, aptr, bhp, o0, o1);
    l_issue(smb + 1 * LSTAGE, 1, aptr, bhp, o0, o1);

#pragma unroll 1
    for (int s = 0; s < KSTEPS; s++) {
        if (s + 1 < KSTEPS)
            asm volatile("cp.async.wait_group 1;" ::: "memory");
        else
            asm volatile("cp.async.wait_group 0;" ::: "memory");
        __syncthreads();
        if (s + 2 < KSTEPS)
            l_issue(smb + (uint32_t)(((s + 2) % 3) * LSTAGE), s + 2,
                    aptr, bhp, o0, o1);

        uint32_t SB = smb + (uint32_t)((s % 3) * LSTAGE);
        U4 ah0 = ldmx4(SB + LT_A + aof[0]);
        U4 ah1 = ldmx4(SB + LT_A + aof[1]);
        U4 ah2 = ldmx4(SB + LT_A + aof[2]);
        U4 ah3 = ldmx4(SB + LT_A + aof[3]);
        U4 bh = ldmx4(SB + LT_BH + bof[0]);
#pragma unroll
        for (int c = 0; c < 4; c++) {
            U4 bhn;
            if (c < 3) bhn = ldmx4(SB + LT_BH + bof[c + 1]);
            mma(d[0][2 * c], ah0, bh.x, bh.y); mma(d[0][2 * c + 1], ah0, bh.z, bh.w);
            mma(d[1][2 * c], ah1, bh.x, bh.y); mma(d[1][2 * c + 1], ah1, bh.z, bh.w);
            mma(d[2][2 * c], ah2, bh.x, bh.y); mma(d[2][2 * c + 1], ah2, bh.z, bh.w);
            mma(d[3][2 * c], ah3, bh.x, bh.y); mma(d[3][2 * c + 1], ah3, bh.z, bh.w);
            bh = bhn;
        }
    }

    // epilogue with bias + per-row stats for the vocab layernorm
    int groupl = lane >> 2, subl = lane & 3;
    int colbase = (int)n0 + warp_n * 64 + subl * 2;
#pragma unroll
    for (int mt = 0; mt < 4; mt++) {
#pragma unroll
        for (int half = 0; half < 2; half++) {
            size_t r = m0 + (size_t)(warp_m * 64 + mt * 16 + half * 8 + groupl);
            float* crow = C + r * (size_t)EXTN + colbase;
            float ssum = 0.f, sq = 0.f;
#pragma unroll
            for (int nt = 0; nt < 8; nt++) {
                float v0 = (half ? d[mt][nt].z : d[mt][nt].x) * BINV;
                float v1 = (half ? d[mt][nt].w : d[mt][nt].y) * BINV;
                v0 += __ldg(bias + colbase + nt * 8);
                v1 += __ldg(bias + colbase + nt * 8 + 1);
                *(float2*)(crow + nt * 8) = make_float2(v0, v1);
                ssum += v0 + v1;
                sq += fmaf(v0, v0, v1 * v1);
            }
            ssum += __shfl_xor_sync(0xffffffffu, ssum, 1);
            ssum += __shfl_xor_sync(0xffffffffu, ssum, 2);
            sq   += __shfl_xor_sync(0xffffffffu, sq, 1);
            sq   += __shfl_xor_sync(0xffffffffu, sq, 2);
            if (subl == 0) {
                atomicAdd(&g_rowsum[r], ssum);
                atomicAdd(&g_rowsq[r], sq);
            }
        }
    }
}

// ---------------- fused additive attention -----------------------------------
__global__ __launch_bounds__(256)
void attn_kernel(const float* __restrict__ src, const float* __restrict__ v_w,
                 const float* __restrict__ W_lin, const float* __restrict__ b_lin) {
    __shared__ float qp[Dd];
    __shared__ float vw[Dd];
    __shared__ float sraw[TK];
    __shared__ float sprob[TK];
    __shared__ float scr[9];

    int row = blockIdx.x;
    int b = row >> 6;
    int tid = threadIdx.x, lane = tid & 31, w = tid >> 5;

    for (int i = tid; i < Dd; i += 256) {
        qp[i] = g_qproj[row * Dd + i];
        vw[i] = v_w[i];
    }
    float tm = g_tgtmask[row];
    __syncthreads();

    float qpr[16], vwr[16];
#pragma unroll
    for (int j = 0; j < 16; j++) {
        qpr[j] = qp[lane + 32 * j];
        vwr[j] = vw[lane + 32 * j];
    }

    for (int k = w; k < TK; k += 8) {
        const float* kp = g_kproj + ((size_t)(b * TK + k)) * Dd;
        float acc = 0.f;
#pragma unroll
        for (int j = 0; j < 16; j++)
            acc += tanh_fast(qpr[j] + __ldg(kp + lane + 32 * j)) * vwr[j];
        acc = warp_sum(acc);
        if (lane == 0) sraw[k] = acc;
    }
    __syncthreads();

    float raw = 0.f, smk = 0.f;
    if (tid < TK) { raw = sraw[tid]; smk = g_srcmask[b * TK + tid]; }
    float masked = (tid < TK) ? ((smk == 0.f) ? -1e30f : raw) : -1e30f;
    float mx = block_max256(masked, scr);
    float e = (tid < TK) ? __expf(masked - mx) : 0.f;
    float ssum = block_sum256(e, scr);
    if (tid < TK) sprob[tid] = e / ssum;

    float oa = (tid < TK) ? raw * smk * tm : 0.f;
    float osum = block_sum256(oa, scr);
    float osq  = block_sum256(oa * oa, scr);

    float zacc = 0.f;
    for (int dd = tid; dd < Dd; dd += 256) {
        float wv = 0.f;
        const float* sp = src + ((size_t)b * TK) * Dd + dd;
#pragma unroll 4
        for (int k = 0; k < TK; k++) wv = fmaf(sprob[k], sp[(size_t)k * Dd], wv);
        wv *= tm;
        zacc = fmaf(wv, W_lin[dd], zacc);
    }
    float z = block_sum256(zacc, scr);
    if (tid == 0) g_p[row] = 1.f / (1.f + __expf(-(z + b_lin[0])));

    float mean = osum * (1.f / (float)TK);
    float var = osq * (1.f / (float)TK) - mean * mean;
    float inv = rsqrtf(var + 1e-5f);
    if (tid < TK) g_att[row * TK + tid] = (oa - mean) * inv;
}

// ---------------- combine (in-place on out) + scatter -------------------------
__global__ __launch_bounds__(256)
void combine_kernel(float* __restrict__ out) {
    int row = blockIdx.x;
    float mean = g_rowsum[row] * (1.f / (float)Vv);
    float var = g_rowsq[row] * (1.f / (float)Vv) - mean * mean;
    float inv = rsqrtf(var + 1e-5f);
    float pv = g_p[row];
    float a = inv * pv;
    float c = -mean * inv * pv;
    float4* op = (float4*)(out + (size_t)row * EXTN);
    for (int i = threadIdx.x; i < Vv / 4; i += 256) {
        float4 v = op[i];
        v.x = fmaf(v.x, a, c); v.y = fmaf(v.y, a, c);
        v.z = fmaf(v.z, a, c); v.w = fmaf(v.w, a, c);
        op[i] = v;
    }
    for (int j = Vv + threadIdx.x; j < EXTN; j += 256)
        out[(size_t)row * EXTN + j] = 0.f;
}

// src_map_idx is int32 on the wire (JAX x64-disabled); bounds-guarded.
__global__ void scatter_kernel(float* __restrict__ out,
                               const int* __restrict__ map) {
    int row = blockIdx.x;
    int b = row >> 6;
    float q = 1.f - g_p[row];
    for (int k = threadIdx.x; k < TK; k += blockDim.x) {
        int idx = map[b * TK + k];
        if (idx >= 0 && idx < EXTN)
            atomicAdd(out + (size_t)row * EXTN + (size_t)idx,
                      q * g_att[row * TK + k]);
    }
}

// ---------------- launch ------------------------------------------------------
extern "C" void kernel_launch(void* const* d_in, const int* in_sizes, int n_in,
                              void* d_out, int out_size) {
    const float* tgt    = (const float*)d_in[0];
    const float* src    = (const float*)d_in[1];
    const int*   mp     = (const int*)d_in[2];
    const float* W_out  = (const float*)d_in[3];
    const float* b_out  = (const float*)d_in[4];
    const float* W_attn = (const float*)d_in[5];
    const float* b_attn = (const float*)d_in[6];
    const float* v_w    = (const float*)d_in[7];
    const float* W_lin  = (const float*)d_in[8];
    const float* b_lin  = (const float*)d_in[9];
    float* out = (float*)d_out;

    static int attr_set = 0;
    if (!attr_set) {
        cudaFuncSetAttribute(qk_gemm, cudaFuncAttributeMaxDynamicSharedMemorySize,
                             GEMM_SMEM);
        cudaFuncSetAttribute(logits_gemm, cudaFuncAttributeMaxDynamicSharedMemorySize,
                             LSMEM);
        attr_set = 1;
    }

    init_kernel<<<2, 256>>>();
    mask_kernel<<<NROW + NKROW, 128>>>(tgt, src);

    // preconvert operands for the vocab GEMM
    {
        int n4 = (int)((size_t)Vv * Dd / 4);
        convert_wout<<<(n4 + 255) / 256, 256>>>((const float4*)W_out, n4);
        n4 = NROW * Dd / 4;
        convert_tgt<<<(n4 + 255) / 256, 256>>>((const float4*)tgt, n4);
    }

    // qproj + kproj merged (z=0: qproj 4 M-blocks; z=1: kproj 8 M-blocks)
    qk_gemm<<<dim3(Dd / 128, NKROW / 128, 2), 128, GEMM_SMEM>>>(
        tgt, src, W_attn, b_attn);

    // logits = tgt @ W_out^T + b_out, written straight into out (ldc = EXTN)
    logits_gemm<<<dim3(Vv / 128, NROW / 128), 128, LSMEM>>>(b_out, out);

    attn_kernel<<<NROW, 256>>>(src, v_w, W_lin, b_lin);
    combine_kernel<<<NROW, 256>>>(out);
    scatter_kernel<<<NROW, 128>>>(out, mp);
}